// round 8
// baseline (speedup 1.0000x reference)
#include <cuda_runtime.h>
#include <math.h>

#define C_CH 8
#define NH 256
#define NW 256
#define OS 320
#define PAD 32
#define NPTS (64*4096)
#define PI_F 3.14159265358979323846

typedef unsigned long long u64;

// ---------------- scratch (static device arrays; no allocation) ----------------
__device__ float2 d_W[OS*OS];                 // centered DFT matrix (symmetric)
__device__ float2 d_Ain[C_CH*NH*NW];          // apodized+scaled input
__device__ float2 d_T[C_CH*NH*OS];            // after row transform (complex)
__device__ __align__(16) float d_Pf[OS*OS*C_CH]; // re(spectrum), packed [y][x][c]

// ---------------- packed f32x2 helpers -----------------------------------------
__device__ __forceinline__ u64 pack2(float lo, float hi) {
    u64 r; asm("mov.b64 %0,{%1,%2};" : "=l"(r) : "f"(lo), "f"(hi)); return r;
}
__device__ __forceinline__ void ffma2(u64& d, u64 a, u64 b) {
    asm("fma.rn.f32x2 %0,%1,%2,%3;" : "=l"(d) : "l"(a), "l"(b), "l"(d));
}
__device__ __forceinline__ float2 unpack2(u64 v) {
    float2 f; asm("mov.b64 {%0,%1},%2;" : "=f"(f.x), "=f"(f.y) : "l"(v)); return f;
}

// ---------------- W matrix: W[k][m] = (-1)^(k+m) * exp(-2pi i k m / 320) ------
__global__ void build_w_kernel() {
    int idx = blockIdx.x * blockDim.x + threadIdx.x;
    if (idx >= OS*OS) return;
    int k = idx / OS, m = idx % OS;
    int r = (k * m) % OS;
    float s, c;
    sincospif(2.0f * (float)r / (float)OS, &s, &c);
    float sign = ((k + m) & 1) ? -1.0f : 1.0f;
    d_W[idx] = make_float2(sign * c, -sign * s);
}

// ---------------- apodization + 1/sqrt(HW) scale ------------------------------
__global__ void prep_kernel(const float* __restrict__ img_r,
                            const float* __restrict__ img_i,
                            float beta2) {
    int idx = blockIdx.x * blockDim.x + threadIdx.x;
    if (idx >= C_CH*NH*NW) return;
    int j = idx % NW;
    int h = (idx / NW) % NH;
    float u, arg, fh, fj;
    u   = (float)PI_F * 6.0f * (float)(h - 128) / 320.0f;
    arg = sqrtf(beta2 - u*u);
    fh  = arg / sinhf(arg);
    u   = (float)PI_F * 6.0f * (float)(j - 128) / 320.0f;
    arg = sqrtf(beta2 - u*u);
    fj  = arg / sinhf(arg);
    float s = fh * fj * (1.0f / 256.0f);
    d_Ain[idx] = make_float2(img_r[idx] * s, img_i[idx] * s);
}

// =================== stage1: complex GEMM, f32x2, 32x64 tile, 128 thr ==========
// T[c][h][k] = sum_j Ain[c][h][j] * W[32+j][k]   (M=256, N=320, K=256)
// acc packed over ROW PAIRS: rows (2*tmi + 16*i2, +1), cols tni + 16*j
__global__ void __launch_bounds__(128) stage1_kernel() {
    __shared__ __align__(16) float Asr[16][34];   // re(a)
    __shared__ __align__(16) float Asi[16][34];   // im(a)
    __shared__ __align__(16) float Asn[16][34];   // -im(a)
    __shared__ u64 Bsx[16][64];                   // splat(re(b))
    __shared__ u64 Bsy[16][64];                   // splat(im(b))
    const int c = blockIdx.z;
    const float2* __restrict__ A = d_Ain + (size_t)c * NH * NW;
    const float2* __restrict__ B = d_W + (size_t)PAD * OS;
    float2* __restrict__ Cm      = d_T + (size_t)c * NH * OS;

    const int tid = threadIdx.x;
    const int bm = blockIdx.y * 32;
    const int bn = blockIdx.x * 64;
    const int tmi = tid >> 4;     // 0..7
    const int tni = tid & 15;     // 0..15
    const int lak = tid & 15, lam = tid >> 4;
    const int lbn = tid & 63, lbh = tid >> 6;

    u64 accre[2][4], accim[2][4];
#pragma unroll
    for (int i = 0; i < 2; i++)
#pragma unroll
        for (int j = 0; j < 4; j++) { accre[i][j] = 0ull; accim[i][j] = 0ull; }

    for (int k0 = 0; k0 < NW; k0 += 16) {
#pragma unroll
        for (int p = 0; p < 4; p++) {
            int m = lam + p*8;
            float2 v = A[min((bm + m) * NW + (k0 + lak), NH*NW - 1)];
            Asr[lak][m] = v.x;
            Asi[lak][m] = v.y;
            Asn[lak][m] = -v.y;
        }
#pragma unroll
        for (int p = 0; p < 8; p++) {
            int h = lbh + p*2;
            float2 v = B[min((k0 + h) * OS + (bn + lbn), OS*OS - PAD*OS - 1)];
            Bsx[h][lbn] = pack2(v.x, v.x);
            Bsy[h][lbn] = pack2(v.y, v.y);
        }
        __syncthreads();
#pragma unroll
        for (int kk = 0; kk < 16; kk++) {
            u64 ar[2], ai[2], an[2], bx[4], by[4];
#pragma unroll
            for (int i2 = 0; i2 < 2; i2++) {
                int m = 2*tmi + 16*i2;
                ar[i2] = *reinterpret_cast<const u64*>(&Asr[kk][m]);
                ai[i2] = *reinterpret_cast<const u64*>(&Asi[kk][m]);
                an[i2] = *reinterpret_cast<const u64*>(&Asn[kk][m]);
            }
#pragma unroll
            for (int j = 0; j < 4; j++) {
                bx[j] = Bsx[kk][tni + 16*j];
                by[j] = Bsy[kk][tni + 16*j];
            }
#pragma unroll
            for (int i2 = 0; i2 < 2; i2++)
#pragma unroll
                for (int j = 0; j < 4; j++) {
                    ffma2(accre[i2][j], ar[i2], bx[j]);   // + ar*br
                    ffma2(accre[i2][j], an[i2], by[j]);   // - ai*bi
                    ffma2(accim[i2][j], ar[i2], by[j]);   // + ar*bi
                    ffma2(accim[i2][j], ai[i2], bx[j]);   // + ai*br
                }
        }
        __syncthreads();
    }
#pragma unroll
    for (int i2 = 0; i2 < 2; i2++)
#pragma unroll
        for (int j = 0; j < 4; j++) {
            int r0 = bm + 2*tmi + 16*i2;
            int col = bn + tni + 16*j;
            float2 re = unpack2(accre[i2][j]);
            float2 im = unpack2(accim[i2][j]);
            int ic0 = r0 * OS + col;
            int ic1 = (r0 + 1) * OS + col;
            if (ic0 < NH*OS) Cm[ic0] = make_float2(re.x, im.x);
            if (ic1 < NH*OS) Cm[ic1] = make_float2(re.y, im.y);
        }
}

// =================== stage2: real-part GEMM, f32x2, fused pack =================
// re(G[c][k2][k]) = sum_h [Wr*Tr - Wi*Ti] -> d_Pf[(k2*OS+k)*8+c]
// (M=320, N=320, K=256); acc packed over COLUMN PAIRS: cols (2*tni+32*j2, +1)
__global__ void __launch_bounds__(128) stage2_kernel() {
    __shared__ u64 Wsr[16][33];                   // splat(re(W))
    __shared__ u64 Wsn[16][33];                   // splat(-im(W))
    __shared__ __align__(16) float Tsr[16][66];   // re(T)
    __shared__ __align__(16) float Tsi[16][66];   // im(T)
    const int c = blockIdx.z;
    const float2* __restrict__ A = d_W + PAD;                 // A[m][h], lda=OS
    const float2* __restrict__ B = d_T + (size_t)c * NH * OS; // B[h][n], ldb=OS

    const int tid = threadIdx.x;
    const int bm = blockIdx.y * 32;
    const int bn = blockIdx.x * 64;
    const int tmi = tid >> 4;     // rows tmi + 8*i, i<4
    const int tni = tid & 15;     // col pairs 2*tni + 32*j2, j2<2
    const int lak = tid & 15, lam = tid >> 4;
    const int lbn = tid & 63, lbh = tid >> 6;

    u64 acc[4][2];
#pragma unroll
    for (int i = 0; i < 4; i++)
#pragma unroll
        for (int j = 0; j < 2; j++) acc[i][j] = 0ull;

    for (int k0 = 0; k0 < NH; k0 += 16) {
#pragma unroll
        for (int p = 0; p < 4; p++) {
            int m = lam + p*8;
            float2 v = A[min((bm + m) * OS + (k0 + lak), OS*OS - PAD - 1)];
            Wsr[lak][m] = pack2(v.x, v.x);
            Wsn[lak][m] = pack2(-v.y, -v.y);
        }
#pragma unroll
        for (int p = 0; p < 8; p++) {
            int h = lbh + p*2;
            float2 v = B[min((k0 + h) * OS + (bn + lbn), NH*OS - 1)];
            Tsr[h][lbn] = v.x;
            Tsi[h][lbn] = v.y;
        }
        __syncthreads();
#pragma unroll
        for (int kk = 0; kk < 16; kk++) {
            u64 wr[4], wn[4], tr[2], ti[2];
#pragma unroll
            for (int i = 0; i < 4; i++) {
                wr[i] = Wsr[kk][tmi + 8*i];
                wn[i] = Wsn[kk][tmi + 8*i];
            }
#pragma unroll
            for (int j2 = 0; j2 < 2; j2++) {
                int n = 2*tni + 32*j2;
                tr[j2] = *reinterpret_cast<const u64*>(&Tsr[kk][n]);
                ti[j2] = *reinterpret_cast<const u64*>(&Tsi[kk][n]);
            }
#pragma unroll
            for (int i = 0; i < 4; i++)
#pragma unroll
                for (int j2 = 0; j2 < 2; j2++) {
                    ffma2(acc[i][j2], wr[i], tr[j2]);   // + Wr*Tr
                    ffma2(acc[i][j2], wn[i], ti[j2]);   // - Wi*Ti
                }
        }
        __syncthreads();
    }
#pragma unroll
    for (int i = 0; i < 4; i++)
#pragma unroll
        for (int j2 = 0; j2 < 2; j2++) {
            int row = bm + tmi + 8*i;
            int col = bn + 2*tni + 32*j2;
            float2 v = unpack2(acc[i][j2]);
            int ip0 = (row * OS + col) * C_CH + c;
            int ip1 = (row * OS + col + 1) * C_CH + c;
            if (ip0 < OS*OS*C_CH) d_Pf[ip0] = v.x;
            if (ip1 < OS*OS*C_CH) d_Pf[ip1] = v.y;
        }
}

// ---------------- Kaiser-Bessel i0 (Abramowitz & Stegun 9.8.1 / 9.8.2) --------
__device__ __forceinline__ float i0f(float x) {
    if (x < 3.75f) {
        float t = x * (1.0f / 3.75f);
        t *= t;
        return 1.0f + t*(3.5156229f + t*(3.0899424f + t*(1.2067492f +
                     t*(0.2659732f + t*(0.0360768f + t*0.0045813f)))));
    } else {
        float t = 3.75f / x;
        float p = 0.39894228f + t*(0.01328592f + t*(0.00225319f +
                  t*(-0.00157565f + t*(0.00916281f + t*(-0.02057706f +
                  t*(0.02635537f + t*(-0.01647633f + t*0.00392377f)))))));
        return expf(x) * rsqrtf(x) * p;
    }
}

// ---------------- KB interpolation: 6x6 gather, 8 real channels per point -----
__global__ void __launch_bounds__(256) interp_kernel(const float* __restrict__ trj,
                              float* __restrict__ out, float beta,
                              int out_floats) {
    int p = blockIdx.x * blockDim.x + threadIdx.x;
    if (p >= NPTS) return;
    float tx = trj[2*p], ty = trj[2*p + 1];
    float cx = __fadd_rn(__fmul_rn(tx, 1.25f), 160.0f);
    float cy = __fadd_rn(__fmul_rn(ty, 1.25f), 160.0f);
    float x0 = ceilf(cx - 3.0f);
    float y0 = ceilf(cy - 3.0f);

    float wx[6], wy[6];
    int   ox[6], oy[6];
#pragma unroll
    for (int d = 0; d < 6; d++) {
        float px = x0 + (float)d;
        float u  = (px - cx) / 3.0f;
        wx[d] = i0f(beta * sqrtf(fmaxf(1.0f - u*u, 0.0f)));
        int q = (int)px % OS; if (q < 0) q += OS;
        ox[d] = q * (OS * C_CH);

        float py = y0 + (float)d;
        u = (py - cy) / 3.0f;
        wy[d] = i0f(beta * sqrtf(fmaxf(1.0f - u*u, 0.0f)));
        q = (int)py % OS; if (q < 0) q += OS;
        oy[d] = q * C_CH;
    }

    float acc[8];
#pragma unroll
    for (int c = 0; c < 8; c++) acc[c] = 0.f;

#pragma unroll
    for (int dx = 0; dx < 6; dx++) {
#pragma unroll
        for (int dy = 0; dy < 6; dy++) {
            float w = wx[dx] * wy[dy];
            int base = min(ox[dx] + oy[dy], OS*OS*C_CH - 8);
            const float4* g = reinterpret_cast<const float4*>(&d_Pf[base]);
            float4 v0 = __ldg(g);
            float4 v1 = __ldg(g + 1);
            acc[0] = fmaf(w, v0.x, acc[0]);
            acc[1] = fmaf(w, v0.y, acc[1]);
            acc[2] = fmaf(w, v0.z, acc[2]);
            acc[3] = fmaf(w, v0.w, acc[3]);
            acc[4] = fmaf(w, v1.x, acc[4]);
            acc[5] = fmaf(w, v1.y, acc[5]);
            acc[6] = fmaf(w, v1.z, acc[6]);
            acc[7] = fmaf(w, v1.w, acc[7]);
        }
    }

    const float inv36 = 1.0f / 36.0f;
#pragma unroll
    for (int c = 0; c < 8; c++) {
        int idx = c * NPTS + p;
        if (idx < out_floats) out[idx] = acc[c] * inv36;
    }
}

// ---------------- launch -------------------------------------------------------
extern "C" void kernel_launch(void* const* d_in, const int* in_sizes, int n_in,
                              void* d_out, int out_size) {
    const float* img_r = (const float*)d_in[0];
    const float* img_i = (const float*)d_in[1];
    const float* trj   = (const float*)d_in[2];
    float* out = (float*)d_out;

    double beta_d = PI_F * sqrt(12.16);
    float beta  = (float)beta_d;
    float beta2 = (float)(beta_d * beta_d);

    build_w_kernel<<<(OS*OS + 255) / 256, 256>>>();
    prep_kernel<<<(C_CH*NH*NW + 255) / 256, 256>>>(img_r, img_i, beta2);

    dim3 g1(OS/64, NH/32, C_CH);   // (5, 8, 8) = 320 blocks
    stage1_kernel<<<g1, 128>>>();
    dim3 g2(OS/64, OS/32, C_CH);   // (5, 10, 8) = 400 blocks
    stage2_kernel<<<g2, 128>>>();

    interp_kernel<<<(NPTS + 255) / 256, 256>>>(trj, out, beta, out_size);
}

// round 9
// speedup vs baseline: 1.1074x; 1.1074x over previous
#include <cuda_runtime.h>
#include <math.h>

#define C_CH 8
#define NH 256
#define NW 256
#define OS 320
#define PAD 32
#define NPTS (64*4096)
#define PI_F 3.14159265358979323846

// ---------------- scratch (static device arrays; no allocation) ----------------
__device__ float2 d_W[OS*OS];                 // centered DFT matrix (symmetric)
__device__ float2 d_Ain[C_CH*NH*NW];          // apodized+scaled input
__device__ float2 d_T[C_CH*NH*OS];            // after row transform (complex)
__device__ __align__(16) float d_Pf[OS*OS*C_CH]; // re(spectrum), packed [y][x][c]

// ---------------- W matrix: W[k][m] = (-1)^(k+m) * exp(-2pi i k m / 320) ------
__global__ void build_w_kernel() {
    int idx = blockIdx.x * blockDim.x + threadIdx.x;
    if (idx >= OS*OS) return;
    int k = idx / OS, m = idx % OS;
    int r = (k * m) % OS;
    float s, c;
    sincospif(2.0f * (float)r / (float)OS, &s, &c);
    float sign = ((k + m) & 1) ? -1.0f : 1.0f;
    d_W[idx] = make_float2(sign * c, -sign * s);
}

// ---------------- apodization + 1/sqrt(HW) scale ------------------------------
__global__ void prep_kernel(const float* __restrict__ img_r,
                            const float* __restrict__ img_i,
                            float beta2) {
    int idx = blockIdx.x * blockDim.x + threadIdx.x;
    if (idx >= C_CH*NH*NW) return;
    int j = idx % NW;
    int h = (idx / NW) % NH;
    float u, arg, fh, fj;
    u   = (float)PI_F * 6.0f * (float)(h - 128) / 320.0f;
    arg = sqrtf(beta2 - u*u);
    fh  = arg / sinhf(arg);
    u   = (float)PI_F * 6.0f * (float)(j - 128) / 320.0f;
    arg = sqrtf(beta2 - u*u);
    fj  = arg / sinhf(arg);
    float s = fh * fj * (1.0f / 256.0f);
    d_Ain[idx] = make_float2(img_r[idx] * s, img_i[idx] * s);
}

// =================== stage1: complex GEMM, 32x64 tile, 128 thr =================
// T[c][h][k] = sum_j Ain[c][h][j] * W[32+j][k]   (M=256, N=320, K=256)
// R7 math body + double-buffered smem, reg prefetch, 1 sync/iter
__global__ void __launch_bounds__(128) stage1_kernel() {
    __shared__ float2 As[2][16][33];   // [buf][k][m], odd pad
    __shared__ float2 Bs[2][16][64];   // [buf][k][n]
    const int c = blockIdx.z;
    const float2* __restrict__ A = d_Ain + (size_t)c * NH * NW;  // lda=NW
    const float2* __restrict__ B = d_W + (size_t)PAD * OS;       // ldb=OS
    float2* __restrict__ Cm      = d_T + (size_t)c * NH * OS;    // ldc=OS

    const int tid = threadIdx.x;
    const int bm = blockIdx.y * 32;
    const int bn = blockIdx.x * 64;
    const int tmi = tid >> 4;     // 0..7 -> rows tmi+8i (i<4)
    const int tni = tid & 15;     // 0..15 -> cols tni+16j (j<4)
    const int lak = tid & 15, lam = tid >> 4;   // A loader
    const int lbn = tid & 63, lbh = tid >> 6;   // B loader
    const int AMAX = NH*NW - 1;
    const int BMAX = OS*OS - PAD*OS - 1;

    float2 acc[4][4];
#pragma unroll
    for (int i = 0; i < 4; i++)
#pragma unroll
        for (int j = 0; j < 4; j++) acc[i][j] = make_float2(0.f, 0.f);

    float2 ra[4], rb[8];
    // prologue: tile 0 -> buf 0
#pragma unroll
    for (int p = 0; p < 4; p++)
        ra[p] = A[min((bm + lam + p*8) * NW + lak, AMAX)];
#pragma unroll
    for (int p = 0; p < 8; p++)
        rb[p] = B[min((lbh + p*2) * OS + (bn + lbn), BMAX)];
#pragma unroll
    for (int p = 0; p < 4; p++) As[0][lak][lam + p*8] = ra[p];
#pragma unroll
    for (int p = 0; p < 8; p++) Bs[0][lbh + p*2][lbn] = rb[p];
    __syncthreads();

    const int NT = NW / 16;   // 16
    for (int t = 0; t < NT; t++) {
        const int cur = t & 1, nxt = cur ^ 1;
        const bool more = (t + 1 < NT);
        if (more) {
            int k0 = (t + 1) * 16;
#pragma unroll
            for (int p = 0; p < 4; p++)
                ra[p] = A[min((bm + lam + p*8) * NW + (k0 + lak), AMAX)];
#pragma unroll
            for (int p = 0; p < 8; p++)
                rb[p] = B[min((k0 + lbh + p*2) * OS + (bn + lbn), BMAX)];
        }
#pragma unroll
        for (int kk = 0; kk < 16; kk++) {
            float2 a[4], b[4];
#pragma unroll
            for (int i = 0; i < 4; i++) a[i] = As[cur][kk][tmi + 8*i];
#pragma unroll
            for (int j = 0; j < 4; j++) b[j] = Bs[cur][kk][tni + 16*j];
#pragma unroll
            for (int i = 0; i < 4; i++)
#pragma unroll
                for (int j = 0; j < 4; j++) {
                    acc[i][j].x = fmaf( a[i].x, b[j].x, acc[i][j].x);
                    acc[i][j].x = fmaf(-a[i].y, b[j].y, acc[i][j].x);
                    acc[i][j].y = fmaf( a[i].x, b[j].y, acc[i][j].y);
                    acc[i][j].y = fmaf( a[i].y, b[j].x, acc[i][j].y);
                }
        }
        if (more) {
#pragma unroll
            for (int p = 0; p < 4; p++) As[nxt][lak][lam + p*8] = ra[p];
#pragma unroll
            for (int p = 0; p < 8; p++) Bs[nxt][lbh + p*2][lbn] = rb[p];
        }
        __syncthreads();
    }
#pragma unroll
    for (int i = 0; i < 4; i++)
#pragma unroll
        for (int j = 0; j < 4; j++) {
            int ic = (bm + tmi + 8*i) * OS + (bn + tni + 16*j);
            if (ic < NH*OS) Cm[ic] = acc[i][j];
        }
}

// =================== stage2: real-part GEMM, fused pack ========================
// re(G[c][k2][k]) = sum_h [Wr*Tr - Wi*Ti] -> d_Pf[(k2*OS+k)*8+c]
// (M=320, N=320, K=256); R7 math body + double buffer
__global__ void __launch_bounds__(128) stage2_kernel() {
    __shared__ float2 Ws[2][16][33];   // [buf][h][m]
    __shared__ float2 Ts[2][16][64];   // [buf][h][n]
    const int c = blockIdx.z;
    const float2* __restrict__ A = d_W + PAD;                    // A[m][h], lda=OS
    const float2* __restrict__ B = d_T + (size_t)c * NH * OS;    // B[h][n], ldb=OS

    const int tid = threadIdx.x;
    const int bm = blockIdx.y * 32;
    const int bn = blockIdx.x * 64;
    const int tmi = tid >> 4;
    const int tni = tid & 15;
    const int lak = tid & 15, lam = tid >> 4;
    const int lbn = tid & 63, lbh = tid >> 6;
    const int AMAX = OS*OS - PAD - 1;
    const int BMAX = NH*OS - 1;

    float acc[4][4];
#pragma unroll
    for (int i = 0; i < 4; i++)
#pragma unroll
        for (int j = 0; j < 4; j++) acc[i][j] = 0.f;

    float2 ra[4], rb[8];
#pragma unroll
    for (int p = 0; p < 4; p++)
        ra[p] = A[min((bm + lam + p*8) * OS + lak, AMAX)];
#pragma unroll
    for (int p = 0; p < 8; p++)
        rb[p] = B[min((lbh + p*2) * OS + (bn + lbn), BMAX)];
#pragma unroll
    for (int p = 0; p < 4; p++) Ws[0][lak][lam + p*8] = ra[p];
#pragma unroll
    for (int p = 0; p < 8; p++) Ts[0][lbh + p*2][lbn] = rb[p];
    __syncthreads();

    const int NT = NH / 16;   // 16
    for (int t = 0; t < NT; t++) {
        const int cur = t & 1, nxt = cur ^ 1;
        const bool more = (t + 1 < NT);
        if (more) {
            int k0 = (t + 1) * 16;
#pragma unroll
            for (int p = 0; p < 4; p++)
                ra[p] = A[min((bm + lam + p*8) * OS + (k0 + lak), AMAX)];
#pragma unroll
            for (int p = 0; p < 8; p++)
                rb[p] = B[min((k0 + lbh + p*2) * OS + (bn + lbn), BMAX)];
        }
#pragma unroll
        for (int kk = 0; kk < 16; kk++) {
            float2 a[4], b[4];
#pragma unroll
            for (int i = 0; i < 4; i++) a[i] = Ws[cur][kk][tmi + 8*i];
#pragma unroll
            for (int j = 0; j < 4; j++) b[j] = Ts[cur][kk][tni + 16*j];
#pragma unroll
            for (int i = 0; i < 4; i++)
#pragma unroll
                for (int j = 0; j < 4; j++) {
                    acc[i][j] = fmaf( a[i].x, b[j].x, acc[i][j]);
                    acc[i][j] = fmaf(-a[i].y, b[j].y, acc[i][j]);
                }
        }
        if (more) {
#pragma unroll
            for (int p = 0; p < 4; p++) Ws[nxt][lak][lam + p*8] = ra[p];
#pragma unroll
            for (int p = 0; p < 8; p++) Ts[nxt][lbh + p*2][lbn] = rb[p];
        }
        __syncthreads();
    }
#pragma unroll
    for (int i = 0; i < 4; i++)
#pragma unroll
        for (int j = 0; j < 4; j++) {
            int yx = (bm + tmi + 8*i) * OS + (bn + tni + 16*j);
            int ip = yx * C_CH + c;
            if (ip < OS*OS*C_CH) d_Pf[ip] = acc[i][j];
        }
}

// ---------------- Kaiser-Bessel i0 (Abramowitz & Stegun 9.8.1 / 9.8.2) --------
__device__ __forceinline__ float i0f(float x) {
    if (x < 3.75f) {
        float t = x * (1.0f / 3.75f);
        t *= t;
        return 1.0f + t*(3.5156229f + t*(3.0899424f + t*(1.2067492f +
                     t*(0.2659732f + t*(0.0360768f + t*0.0045813f)))));
    } else {
        float t = 3.75f / x;
        float p = 0.39894228f + t*(0.01328592f + t*(0.00225319f +
                  t*(-0.00157565f + t*(0.00916281f + t*(-0.02057706f +
                  t*(0.02635537f + t*(-0.01647633f + t*0.00392377f)))))));
        return expf(x) * rsqrtf(x) * p;
    }
}

// ---------------- KB interpolation: 6x6 gather, 8 real channels per point -----
__global__ void __launch_bounds__(256) interp_kernel(const float* __restrict__ trj,
                              float* __restrict__ out, float beta,
                              int out_floats) {
    int p = blockIdx.x * blockDim.x + threadIdx.x;
    if (p >= NPTS) return;
    float tx = trj[2*p], ty = trj[2*p + 1];
    float cx = __fadd_rn(__fmul_rn(tx, 1.25f), 160.0f);
    float cy = __fadd_rn(__fmul_rn(ty, 1.25f), 160.0f);
    float x0 = ceilf(cx - 3.0f);
    float y0 = ceilf(cy - 3.0f);

    float wx[6], wy[6];
    int   ox[6], oy[6];
#pragma unroll
    for (int d = 0; d < 6; d++) {
        float px = x0 + (float)d;
        float u  = (px - cx) / 3.0f;
        wx[d] = i0f(beta * sqrtf(fmaxf(1.0f - u*u, 0.0f)));
        int q = (int)px % OS; if (q < 0) q += OS;
        ox[d] = q * (OS * C_CH);

        float py = y0 + (float)d;
        u = (py - cy) / 3.0f;
        wy[d] = i0f(beta * sqrtf(fmaxf(1.0f - u*u, 0.0f)));
        q = (int)py % OS; if (q < 0) q += OS;
        oy[d] = q * C_CH;
    }

    float acc[8];
#pragma unroll
    for (int c = 0; c < 8; c++) acc[c] = 0.f;

#pragma unroll
    for (int dx = 0; dx < 6; dx++) {
#pragma unroll
        for (int dy = 0; dy < 6; dy++) {
            float w = wx[dx] * wy[dy];
            int base = min(ox[dx] + oy[dy], OS*OS*C_CH - 8);
            const float4* g = reinterpret_cast<const float4*>(&d_Pf[base]);
            float4 v0 = __ldg(g);
            float4 v1 = __ldg(g + 1);
            acc[0] = fmaf(w, v0.x, acc[0]);
            acc[1] = fmaf(w, v0.y, acc[1]);
            acc[2] = fmaf(w, v0.z, acc[2]);
            acc[3] = fmaf(w, v0.w, acc[3]);
            acc[4] = fmaf(w, v1.x, acc[4]);
            acc[5] = fmaf(w, v1.y, acc[5]);
            acc[6] = fmaf(w, v1.z, acc[6]);
            acc[7] = fmaf(w, v1.w, acc[7]);
        }
    }

    const float inv36 = 1.0f / 36.0f;
#pragma unroll
    for (int c = 0; c < 8; c++) {
        int idx = c * NPTS + p;
        if (idx < out_floats) out[idx] = acc[c] * inv36;
    }
}

// ---------------- launch -------------------------------------------------------
extern "C" void kernel_launch(void* const* d_in, const int* in_sizes, int n_in,
                              void* d_out, int out_size) {
    const float* img_r = (const float*)d_in[0];
    const float* img_i = (const float*)d_in[1];
    const float* trj   = (const float*)d_in[2];
    float* out = (float*)d_out;

    double beta_d = PI_F * sqrt(12.16);
    float beta  = (float)beta_d;
    float beta2 = (float)(beta_d * beta_d);

    build_w_kernel<<<(OS*OS + 255) / 256, 256>>>();
    prep_kernel<<<(C_CH*NH*NW + 255) / 256, 256>>>(img_r, img_i, beta2);

    dim3 g1(OS/64, NH/32, C_CH);   // (5, 8, 8) = 320 blocks
    stage1_kernel<<<g1, 128>>>();
    dim3 g2(OS/64, OS/32, C_CH);   // (5, 10, 8) = 400 blocks
    stage2_kernel<<<g2, 128>>>();

    interp_kernel<<<(NPTS + 255) / 256, 256>>>(trj, out, beta, out_size);
}

// round 10
// speedup vs baseline: 1.2256x; 1.1067x over previous
#include <cuda_runtime.h>
#include <math.h>

#define C_CH 8
#define NH 256
#define NW 256
#define OS 320
#define PAD 32
#define KF 129
#define KFP 144
#define NPTS (64*4096)
#define PI_F 3.14159265358979323846

// ---------------- scratch (static device arrays; no allocation) ----------------
__device__ float2 d_W[OS*OS];                 // centered DFT matrix (stage2 A)
__device__ float2 d_W1[KFP*OS];               // (Wr,Wi) of rows 32..160, zero-pad
__device__ float2 d_S[C_CH*NH*KFP];           // folded input: A[j]+A[256-j]
__device__ float2 d_E[C_CH*NH*KFP];           // folded input: i*(A[j]-A[256-j])
__device__ float2 d_T[C_CH*NH*OS];            // after row transform (complex)
__device__ __align__(16) float d_Pf[OS*OS*C_CH]; // re(spectrum), packed [y][x][c]

// ---------------- W matrix: W[k][m] = (-1)^(k+m) * exp(-2pi i k m / 320) ------
__global__ void build_w_kernel() {
    int idx = blockIdx.x * blockDim.x + threadIdx.x;
    if (idx >= OS*OS) return;
    int k = idx / OS, m = idx % OS;
    int r = (k * m) % OS;
    float s, c;
    sincospif(2.0f * (float)r / (float)OS, &s, &c);
    float sign = ((k + m) & 1) ? -1.0f : 1.0f;
    d_W[idx] = make_float2(sign * c, -sign * s);
}

// W1[jf][k] = W[32+jf][k] for jf<=128, else 0
__global__ void build_w1_kernel() {
    int idx = blockIdx.x * blockDim.x + threadIdx.x;
    if (idx >= KFP*OS) return;
    int jf = idx / OS, k = idx % OS;
    if (jf > 128) { d_W1[idx] = make_float2(0.f, 0.f); return; }
    int row = 32 + jf;
    int r = (row * k) % OS;
    float s, c;
    sincospif(2.0f * (float)r / (float)OS, &s, &c);
    float sign = ((row + k) & 1) ? -1.0f : 1.0f;
    d_W1[idx] = make_float2(sign * c, -sign * s);
}

// ---------------- prep: apodize + scale + conjugate-pair fold ------------------
// S[j] = s*(A[j]+M), E[j] = i*s*(A[j]-M), M = A[256-j] for j in 1..127 else 0
__global__ void prep_kernel(const float* __restrict__ img_r,
                            const float* __restrict__ img_i,
                            float beta2) {
    int idx = blockIdx.x * blockDim.x + threadIdx.x;
    if (idx >= C_CH*NH*KFP) return;
    int jf = idx % KFP;
    int h  = (idx / KFP) % NH;
    int c  = idx / (KFP * NH);
    if (jf > 128) { d_S[idx] = make_float2(0.f,0.f); d_E[idx] = make_float2(0.f,0.f); return; }
    float u, arg;
    u   = (float)PI_F * 6.0f * (float)(h - 128) / 320.0f;
    arg = sqrtf(beta2 - u*u);
    float fh = arg / sinhf(arg);
    u   = (float)PI_F * 6.0f * (float)(jf - 128) / 320.0f;
    arg = sqrtf(beta2 - u*u);
    float fj = arg / sinhf(arg);
    float s = fh * fj * (1.0f / 256.0f);

    int base = (c * NH + h) * NW;
    float ar = img_r[base + jf], ai = img_i[base + jf];
    float mr = 0.f, mi = 0.f;
    if (jf >= 1 && jf <= 127) {
        mr = img_r[base + 256 - jf];
        mi = img_i[base + 256 - jf];
    }
    float Sr = s * (ar + mr), Si = s * (ai + mi);
    float Dr = s * (ar - mr), Di = s * (ai - mi);
    d_S[idx] = make_float2(Sr, Si);
    d_E[idx] = make_float2(-Di, Dr);     // i*D
}

// =================== stage1: folded complex GEMM, 32x64 tile, 128 thr ==========
// T[c][h][k] = sum_{jf=0..143} S[h][jf]*Wr1[jf][k] + E[h][jf]*Wi1[jf][k]
// (M=256, N=320, K=144), double-buffered
__global__ void __launch_bounds__(128) stage1_kernel() {
    __shared__ float2 Ss[2][16][33];
    __shared__ float2 Es[2][16][33];
    __shared__ float  Wrs[2][16][64];
    __shared__ float  Wis[2][16][64];
    const int c = blockIdx.z;
    const float2* __restrict__ Sg = d_S + (size_t)c * NH * KFP;
    const float2* __restrict__ Eg = d_E + (size_t)c * NH * KFP;
    float2* __restrict__ Cm       = d_T + (size_t)c * NH * OS;

    const int tid = threadIdx.x;
    const int bm = blockIdx.y * 32;
    const int bn = blockIdx.x * 64;
    const int tmi = tid >> 4;     // rows tmi+8i
    const int tni = tid & 15;     // cols tni+16j
    const int lak = tid & 15, lam = tid >> 4;
    const int lbn = tid & 63, lbh = tid >> 6;
    const int AMAX = NH*KFP - 1;
    const int BMAX = KFP*OS - 1;

    float2 acc[4][4];
#pragma unroll
    for (int i = 0; i < 4; i++)
#pragma unroll
        for (int j = 0; j < 4; j++) acc[i][j] = make_float2(0.f, 0.f);

    float2 rs[4], re_[4], rw[8];
    // prologue: tile 0
#pragma unroll
    for (int p = 0; p < 4; p++) {
        int ia = (bm + lam + p*8) * KFP + lak;
        rs[p]  = Sg[min(ia, AMAX)];
        re_[p] = Eg[min(ia, AMAX)];
    }
#pragma unroll
    for (int p = 0; p < 8; p++)
        rw[p] = d_W1[min((lbh + p*2) * OS + (bn + lbn), BMAX)];
#pragma unroll
    for (int p = 0; p < 4; p++) { Ss[0][lak][lam+p*8] = rs[p]; Es[0][lak][lam+p*8] = re_[p]; }
#pragma unroll
    for (int p = 0; p < 8; p++) { Wrs[0][lbh+p*2][lbn] = rw[p].x; Wis[0][lbh+p*2][lbn] = rw[p].y; }
    __syncthreads();

    const int NT = KFP / 16;   // 9
    for (int t = 0; t < NT; t++) {
        const int cur = t & 1, nxt = cur ^ 1;
        const bool more = (t + 1 < NT);
        if (more) {
            int k0 = (t + 1) * 16;
#pragma unroll
            for (int p = 0; p < 4; p++) {
                int ia = (bm + lam + p*8) * KFP + (k0 + lak);
                rs[p]  = Sg[min(ia, AMAX)];
                re_[p] = Eg[min(ia, AMAX)];
            }
#pragma unroll
            for (int p = 0; p < 8; p++)
                rw[p] = d_W1[min((k0 + lbh + p*2) * OS + (bn + lbn), BMAX)];
        }
#pragma unroll
        for (int kk = 0; kk < 16; kk++) {
            float2 s[4], e[4];
            float wr[4], wi[4];
#pragma unroll
            for (int i = 0; i < 4; i++) { s[i] = Ss[cur][kk][tmi+8*i]; e[i] = Es[cur][kk][tmi+8*i]; }
#pragma unroll
            for (int j = 0; j < 4; j++) { wr[j] = Wrs[cur][kk][tni+16*j]; wi[j] = Wis[cur][kk][tni+16*j]; }
#pragma unroll
            for (int i = 0; i < 4; i++)
#pragma unroll
                for (int j = 0; j < 4; j++) {
                    acc[i][j].x = fmaf(s[i].x, wr[j], acc[i][j].x);
                    acc[i][j].x = fmaf(e[i].x, wi[j], acc[i][j].x);
                    acc[i][j].y = fmaf(s[i].y, wr[j], acc[i][j].y);
                    acc[i][j].y = fmaf(e[i].y, wi[j], acc[i][j].y);
                }
        }
        if (more) {
#pragma unroll
            for (int p = 0; p < 4; p++) { Ss[nxt][lak][lam+p*8] = rs[p]; Es[nxt][lak][lam+p*8] = re_[p]; }
#pragma unroll
            for (int p = 0; p < 8; p++) { Wrs[nxt][lbh+p*2][lbn] = rw[p].x; Wis[nxt][lbh+p*2][lbn] = rw[p].y; }
        }
        __syncthreads();
    }
#pragma unroll
    for (int i = 0; i < 4; i++)
#pragma unroll
        for (int j = 0; j < 4; j++) {
            int ic = (bm + tmi + 8*i) * OS + (bn + tni + 16*j);
            if (ic < NH*OS) Cm[ic] = acc[i][j];
        }
}

// =================== stage2: folded real-part GEMM, fused pack =================
// P = sum Wr[m][h]*Tr[h][n], Q = sum Wi[m][h]*Ti[h][n]
// re(G)[m] = P-Q (m=0..191 direct); re(G)[320-m] = P+Q (written iff 320-m>=192)
__global__ void __launch_bounds__(128) stage2_kernel() {
    __shared__ float Wr2s[2][16][33];
    __shared__ float Wi2s[2][16][33];
    __shared__ float Trs[2][16][64];
    __shared__ float Tis[2][16][64];
    const int c = blockIdx.z;
    const float2* __restrict__ A = d_W + PAD;                    // A[m][h]=W[m][32+h]
    const float2* __restrict__ B = d_T + (size_t)c * NH * OS;    // B[h][n]

    const int tid = threadIdx.x;
    const int bm = blockIdx.y * 32;   // m in [0,192)
    const int bn = blockIdx.x * 64;
    const int tmi = tid >> 4;
    const int tni = tid & 15;
    const int lak = tid & 15, lam = tid >> 4;
    const int lbn = tid & 63, lbh = tid >> 6;
    const int AMAX = OS*OS - PAD - 1;
    const int BMAX = NH*OS - 1;

    float accP[4][4], accQ[4][4];
#pragma unroll
    for (int i = 0; i < 4; i++)
#pragma unroll
        for (int j = 0; j < 4; j++) { accP[i][j] = 0.f; accQ[i][j] = 0.f; }

    float2 ra[4], rb[8];
#pragma unroll
    for (int p = 0; p < 4; p++)
        ra[p] = A[min((bm + lam + p*8) * OS + lak, AMAX)];
#pragma unroll
    for (int p = 0; p < 8; p++)
        rb[p] = B[min((lbh + p*2) * OS + (bn + lbn), BMAX)];
#pragma unroll
    for (int p = 0; p < 4; p++) { Wr2s[0][lak][lam+p*8] = ra[p].x; Wi2s[0][lak][lam+p*8] = ra[p].y; }
#pragma unroll
    for (int p = 0; p < 8; p++) { Trs[0][lbh+p*2][lbn] = rb[p].x; Tis[0][lbh+p*2][lbn] = rb[p].y; }
    __syncthreads();

    const int NT = NH / 16;   // 16
    for (int t = 0; t < NT; t++) {
        const int cur = t & 1, nxt = cur ^ 1;
        const bool more = (t + 1 < NT);
        if (more) {
            int k0 = (t + 1) * 16;
#pragma unroll
            for (int p = 0; p < 4; p++)
                ra[p] = A[min((bm + lam + p*8) * OS + (k0 + lak), AMAX)];
#pragma unroll
            for (int p = 0; p < 8; p++)
                rb[p] = B[min((k0 + lbh + p*2) * OS + (bn + lbn), BMAX)];
        }
#pragma unroll
        for (int kk = 0; kk < 16; kk++) {
            float wr[4], wi[4], tr[4], ti[4];
#pragma unroll
            for (int i = 0; i < 4; i++) { wr[i] = Wr2s[cur][kk][tmi+8*i]; wi[i] = Wi2s[cur][kk][tmi+8*i]; }
#pragma unroll
            for (int j = 0; j < 4; j++) { tr[j] = Trs[cur][kk][tni+16*j]; ti[j] = Tis[cur][kk][tni+16*j]; }
#pragma unroll
            for (int i = 0; i < 4; i++)
#pragma unroll
                for (int j = 0; j < 4; j++) {
                    accP[i][j] = fmaf(wr[i], tr[j], accP[i][j]);
                    accQ[i][j] = fmaf(wi[i], ti[j], accQ[i][j]);
                }
        }
        if (more) {
#pragma unroll
            for (int p = 0; p < 4; p++) { Wr2s[nxt][lak][lam+p*8] = ra[p].x; Wi2s[nxt][lak][lam+p*8] = ra[p].y; }
#pragma unroll
            for (int p = 0; p < 8; p++) { Trs[nxt][lbh+p*2][lbn] = rb[p].x; Tis[nxt][lbh+p*2][lbn] = rb[p].y; }
        }
        __syncthreads();
    }
#pragma unroll
    for (int i = 0; i < 4; i++)
#pragma unroll
        for (int j = 0; j < 4; j++) {
            int m   = bm + tmi + 8*i;
            int col = bn + tni + 16*j;
            int ip  = (m * OS + col) * C_CH + c;
            if (ip < OS*OS*C_CH) d_Pf[ip] = accP[i][j] - accQ[i][j];
            int mm = 320 - m;
            if (mm >= 192 && mm < 320) {
                int ipm = (mm * OS + col) * C_CH + c;
                d_Pf[ipm] = accP[i][j] + accQ[i][j];
            }
        }
}

// ---------------- Kaiser-Bessel i0 (Abramowitz & Stegun 9.8.1 / 9.8.2) --------
__device__ __forceinline__ float i0f(float x) {
    if (x < 3.75f) {
        float t = x * (1.0f / 3.75f);
        t *= t;
        return 1.0f + t*(3.5156229f + t*(3.0899424f + t*(1.2067492f +
                     t*(0.2659732f + t*(0.0360768f + t*0.0045813f)))));
    } else {
        float t = 3.75f / x;
        float p = 0.39894228f + t*(0.01328592f + t*(0.00225319f +
                  t*(-0.00157565f + t*(0.00916281f + t*(-0.02057706f +
                  t*(0.02635537f + t*(-0.01647633f + t*0.00392377f)))))));
        return expf(x) * rsqrtf(x) * p;
    }
}

// ---------------- KB interpolation: 6x6 gather, 8 real channels per point -----
__global__ void __launch_bounds__(256) interp_kernel(const float* __restrict__ trj,
                              float* __restrict__ out, float beta,
                              int out_floats) {
    int p = blockIdx.x * blockDim.x + threadIdx.x;
    if (p >= NPTS) return;
    float tx = trj[2*p], ty = trj[2*p + 1];
    float cx = __fadd_rn(__fmul_rn(tx, 1.25f), 160.0f);
    float cy = __fadd_rn(__fmul_rn(ty, 1.25f), 160.0f);
    float x0 = ceilf(cx - 3.0f);
    float y0 = ceilf(cy - 3.0f);

    float wx[6], wy[6];
    int   ox[6], oy[6];
#pragma unroll
    for (int d = 0; d < 6; d++) {
        float px = x0 + (float)d;
        float u  = (px - cx) / 3.0f;
        wx[d] = i0f(beta * sqrtf(fmaxf(1.0f - u*u, 0.0f)));
        int q = (int)px % OS; if (q < 0) q += OS;
        ox[d] = q * (OS * C_CH);

        float py = y0 + (float)d;
        u = (py - cy) / 3.0f;
        wy[d] = i0f(beta * sqrtf(fmaxf(1.0f - u*u, 0.0f)));
        q = (int)py % OS; if (q < 0) q += OS;
        oy[d] = q * C_CH;
    }

    float acc[8];
#pragma unroll
    for (int c = 0; c < 8; c++) acc[c] = 0.f;

#pragma unroll
    for (int dx = 0; dx < 6; dx++) {
#pragma unroll
        for (int dy = 0; dy < 6; dy++) {
            float w = wx[dx] * wy[dy];
            int base = min(ox[dx] + oy[dy], OS*OS*C_CH - 8);
            const float4* g = reinterpret_cast<const float4*>(&d_Pf[base]);
            float4 v0 = __ldg(g);
            float4 v1 = __ldg(g + 1);
            acc[0] = fmaf(w, v0.x, acc[0]);
            acc[1] = fmaf(w, v0.y, acc[1]);
            acc[2] = fmaf(w, v0.z, acc[2]);
            acc[3] = fmaf(w, v0.w, acc[3]);
            acc[4] = fmaf(w, v1.x, acc[4]);
            acc[5] = fmaf(w, v1.y, acc[5]);
            acc[6] = fmaf(w, v1.z, acc[6]);
            acc[7] = fmaf(w, v1.w, acc[7]);
        }
    }

    const float inv36 = 1.0f / 36.0f;
#pragma unroll
    for (int c = 0; c < 8; c++) {
        int idx = c * NPTS + p;
        if (idx < out_floats) out[idx] = acc[c] * inv36;
    }
}

// ---------------- launch -------------------------------------------------------
extern "C" void kernel_launch(void* const* d_in, const int* in_sizes, int n_in,
                              void* d_out, int out_size) {
    const float* img_r = (const float*)d_in[0];
    const float* img_i = (const float*)d_in[1];
    const float* trj   = (const float*)d_in[2];
    float* out = (float*)d_out;

    double beta_d = PI_F * sqrt(12.16);
    float beta  = (float)beta_d;
    float beta2 = (float)(beta_d * beta_d);

    build_w_kernel<<<(OS*OS + 255) / 256, 256>>>();
    build_w1_kernel<<<(KFP*OS + 255) / 256, 256>>>();
    prep_kernel<<<(C_CH*NH*KFP + 255) / 256, 256>>>(img_r, img_i, beta2);

    dim3 g1(OS/64, NH/32, C_CH);   // (5, 8, 8) = 320 blocks
    stage1_kernel<<<g1, 128>>>();
    dim3 g2(OS/64, 6, C_CH);       // (5, 6, 8) = 240 blocks, m=0..191
    stage2_kernel<<<g2, 128>>>();

    interp_kernel<<<(NPTS + 255) / 256, 256>>>(trj, out, beta, out_size);
}

// round 11
// speedup vs baseline: 1.3110x; 1.0697x over previous
#include <cuda_runtime.h>
#include <math.h>

#define C_CH 8
#define NH 256
#define NW 256
#define OS 320
#define PAD 32
#define KF 129
#define KFP 144
#define NPTS (64*4096)
#define PI_F 3.14159265358979323846

// ---------------- scratch (static device arrays; no allocation) ----------------
__device__ float2 d_W[OS*OS];                 // centered DFT matrix (stage2 A)
__device__ float2 d_W1[KFP*OS];               // (Wr,Wi) of rows 32..160, zero-pad
__device__ float2 d_S[C_CH*NH*KFP];           // folded input: A[j]+A[256-j]
__device__ float2 d_E[C_CH*NH*KFP];           // folded input: i*(A[j]-A[256-j])
__device__ float2 d_T[C_CH*NH*OS];            // after row transform (complex)
__device__ __align__(16) float d_Pf[OS*OS*C_CH]; // re(spectrum), packed [y][x][c]

// ---------------- build W and W1 in one launch ---------------------------------
__global__ void build_all_w_kernel() {
    int idx = blockIdx.x * blockDim.x + threadIdx.x;
    if (idx < OS*OS) {
        int k = idx / OS, m = idx % OS;
        int r = (k * m) % OS;
        float s, c;
        sincospif(2.0f * (float)r / (float)OS, &s, &c);
        float sign = ((k + m) & 1) ? -1.0f : 1.0f;
        d_W[idx] = make_float2(sign * c, -sign * s);
        return;
    }
    int i2 = idx - OS*OS;
    if (i2 >= KFP*OS) return;
    int jf = i2 / OS, k = i2 % OS;
    if (jf > 128) { d_W1[i2] = make_float2(0.f, 0.f); return; }
    int row = 32 + jf;
    int r = (row * k) % OS;
    float s, c;
    sincospif(2.0f * (float)r / (float)OS, &s, &c);
    float sign = ((row + k) & 1) ? -1.0f : 1.0f;
    d_W1[i2] = make_float2(sign * c, -sign * s);
}

// ---------------- prep: apodize + scale + conjugate-pair fold ------------------
__global__ void prep_kernel(const float* __restrict__ img_r,
                            const float* __restrict__ img_i,
                            float beta2) {
    int idx = blockIdx.x * blockDim.x + threadIdx.x;
    if (idx >= C_CH*NH*KFP) return;
    int jf = idx % KFP;
    int h  = (idx / KFP) % NH;
    int c  = idx / (KFP * NH);
    if (jf > 128) { d_S[idx] = make_float2(0.f,0.f); d_E[idx] = make_float2(0.f,0.f); return; }
    float u, arg;
    u   = (float)PI_F * 6.0f * (float)(h - 128) / 320.0f;
    arg = sqrtf(beta2 - u*u);
    float fh = arg / sinhf(arg);
    u   = (float)PI_F * 6.0f * (float)(jf - 128) / 320.0f;
    arg = sqrtf(beta2 - u*u);
    float fj = arg / sinhf(arg);
    float s = fh * fj * (1.0f / 256.0f);

    int base = (c * NH + h) * NW;
    float ar = img_r[base + jf], ai = img_i[base + jf];
    float mr = 0.f, mi = 0.f;
    if (jf >= 1 && jf <= 127) {
        mr = img_r[base + 256 - jf];
        mi = img_i[base + 256 - jf];
    }
    float Sr = s * (ar + mr), Si = s * (ai + mi);
    float Dr = s * (ar - mr), Di = s * (ai - mi);
    d_S[idx] = make_float2(Sr, Si);
    d_E[idx] = make_float2(-Di, Dr);     // i*D
}

// ========== stage1: doubly-folded GEMM, col pairs, 32x(64 pair) tile ===========
// P = sum_jf S*Wr1, Q = sum_jf E*Wi1  (complex P,Q; scalar weights)
// T[h][q] = P+Q (q=0..191); T[h][320-q] = P-Q (written iff q in [1,128])
// (M=256, N=192 pairs, K=144), double-buffered; grid (3, 8, 8) = 192 blocks
__global__ void __launch_bounds__(128) stage1_kernel() {
    __shared__ float2 Ss[2][16][33];
    __shared__ float2 Es[2][16][33];
    __shared__ float2 Wv[2][16][64];   // (Wr, Wi)
    const int c = blockIdx.z;
    const float2* __restrict__ Sg = d_S + (size_t)c * NH * KFP;
    const float2* __restrict__ Eg = d_E + (size_t)c * NH * KFP;
    float2* __restrict__ Cm       = d_T + (size_t)c * NH * OS;

    const int tid = threadIdx.x;
    const int bm = blockIdx.y * 32;   // h rows
    const int bq = blockIdx.x * 64;   // col-pair base (0,64,128)
    const int tmi = tid >> 4;         // rows tmi+8i
    const int tni = tid & 15;         // pairs tni+16j
    const int lak = tid & 15, lam = tid >> 4;
    const int lbn = tid & 63, lbh = tid >> 6;
    const int AMAX = NH*KFP - 1;
    const int BMAX = KFP*OS - 1;

    float2 P[4][4], Q[4][4];
#pragma unroll
    for (int i = 0; i < 4; i++)
#pragma unroll
        for (int j = 0; j < 4; j++) { P[i][j] = make_float2(0.f,0.f); Q[i][j] = make_float2(0.f,0.f); }

    float2 rs[4], re_[4], rw[8];
#pragma unroll
    for (int p = 0; p < 4; p++) {
        int ia = (bm + lam + p*8) * KFP + lak;
        rs[p]  = Sg[min(ia, AMAX)];
        re_[p] = Eg[min(ia, AMAX)];
    }
#pragma unroll
    for (int p = 0; p < 8; p++)
        rw[p] = d_W1[min((lbh + p*2) * OS + (bq + lbn), BMAX)];
#pragma unroll
    for (int p = 0; p < 4; p++) { Ss[0][lak][lam+p*8] = rs[p]; Es[0][lak][lam+p*8] = re_[p]; }
#pragma unroll
    for (int p = 0; p < 8; p++) Wv[0][lbh+p*2][lbn] = rw[p];
    __syncthreads();

    const int NT = KFP / 16;   // 9
    for (int t = 0; t < NT; t++) {
        const int cur = t & 1, nxt = cur ^ 1;
        const bool more = (t + 1 < NT);
        if (more) {
            int k0 = (t + 1) * 16;
#pragma unroll
            for (int p = 0; p < 4; p++) {
                int ia = (bm + lam + p*8) * KFP + (k0 + lak);
                rs[p]  = Sg[min(ia, AMAX)];
                re_[p] = Eg[min(ia, AMAX)];
            }
#pragma unroll
            for (int p = 0; p < 8; p++)
                rw[p] = d_W1[min((k0 + lbh + p*2) * OS + (bq + lbn), BMAX)];
        }
#pragma unroll
        for (int kk = 0; kk < 16; kk++) {
            float2 s[4], e[4], w[4];
#pragma unroll
            for (int i = 0; i < 4; i++) { s[i] = Ss[cur][kk][tmi+8*i]; e[i] = Es[cur][kk][tmi+8*i]; }
#pragma unroll
            for (int j = 0; j < 4; j++) w[j] = Wv[cur][kk][tni+16*j];
#pragma unroll
            for (int i = 0; i < 4; i++)
#pragma unroll
                for (int j = 0; j < 4; j++) {
                    P[i][j].x = fmaf(s[i].x, w[j].x, P[i][j].x);
                    P[i][j].y = fmaf(s[i].y, w[j].x, P[i][j].y);
                    Q[i][j].x = fmaf(e[i].x, w[j].y, Q[i][j].x);
                    Q[i][j].y = fmaf(e[i].y, w[j].y, Q[i][j].y);
                }
        }
        if (more) {
#pragma unroll
            for (int p = 0; p < 4; p++) { Ss[nxt][lak][lam+p*8] = rs[p]; Es[nxt][lak][lam+p*8] = re_[p]; }
#pragma unroll
            for (int p = 0; p < 8; p++) Wv[nxt][lbh+p*2][lbn] = rw[p];
        }
        __syncthreads();
    }
#pragma unroll
    for (int i = 0; i < 4; i++)
#pragma unroll
        for (int j = 0; j < 4; j++) {
            int row = bm + tmi + 8*i;
            int q   = bq + tni + 16*j;
            int ic  = row * OS + q;
            if (ic < NH*OS)
                Cm[ic] = make_float2(P[i][j].x + Q[i][j].x, P[i][j].y + Q[i][j].y);
            if (q >= 1 && q <= 128) {
                int icm = row * OS + (320 - q);
                Cm[icm] = make_float2(P[i][j].x - Q[i][j].x, P[i][j].y - Q[i][j].y);
            }
        }
}

// =================== stage2: folded real-part GEMM, fused pack =================
// P = sum Wr[m][h]*Tr[h][n], Q = sum Wi[m][h]*Ti[h][n]
// re(G)[m] = P-Q (m=0..191); re(G)[320-m] = P+Q (written iff 320-m>=192)
__global__ void __launch_bounds__(128) stage2_kernel() {
    __shared__ float Wr2s[2][16][33];
    __shared__ float Wi2s[2][16][33];
    __shared__ float Trs[2][16][64];
    __shared__ float Tis[2][16][64];
    const int c = blockIdx.z;
    const float2* __restrict__ A = d_W + PAD;                    // A[m][h]=W[m][32+h]
    const float2* __restrict__ B = d_T + (size_t)c * NH * OS;    // B[h][n]

    const int tid = threadIdx.x;
    const int bm = blockIdx.y * 32;   // m in [0,192)
    const int bn = blockIdx.x * 64;
    const int tmi = tid >> 4;
    const int tni = tid & 15;
    const int lak = tid & 15, lam = tid >> 4;
    const int lbn = tid & 63, lbh = tid >> 6;
    const int AMAX = OS*OS - PAD - 1;
    const int BMAX = NH*OS - 1;

    float accP[4][4], accQ[4][4];
#pragma unroll
    for (int i = 0; i < 4; i++)
#pragma unroll
        for (int j = 0; j < 4; j++) { accP[i][j] = 0.f; accQ[i][j] = 0.f; }

    float2 ra[4], rb[8];
#pragma unroll
    for (int p = 0; p < 4; p++)
        ra[p] = A[min((bm + lam + p*8) * OS + lak, AMAX)];
#pragma unroll
    for (int p = 0; p < 8; p++)
        rb[p] = B[min((lbh + p*2) * OS + (bn + lbn), BMAX)];
#pragma unroll
    for (int p = 0; p < 4; p++) { Wr2s[0][lak][lam+p*8] = ra[p].x; Wi2s[0][lak][lam+p*8] = ra[p].y; }
#pragma unroll
    for (int p = 0; p < 8; p++) { Trs[0][lbh+p*2][lbn] = rb[p].x; Tis[0][lbh+p*2][lbn] = rb[p].y; }
    __syncthreads();

    const int NT = NH / 16;   // 16
    for (int t = 0; t < NT; t++) {
        const int cur = t & 1, nxt = cur ^ 1;
        const bool more = (t + 1 < NT);
        if (more) {
            int k0 = (t + 1) * 16;
#pragma unroll
            for (int p = 0; p < 4; p++)
                ra[p] = A[min((bm + lam + p*8) * OS + (k0 + lak), AMAX)];
#pragma unroll
            for (int p = 0; p < 8; p++)
                rb[p] = B[min((k0 + lbh + p*2) * OS + (bn + lbn), BMAX)];
        }
#pragma unroll
        for (int kk = 0; kk < 16; kk++) {
            float wr[4], wi[4], tr[4], ti[4];
#pragma unroll
            for (int i = 0; i < 4; i++) { wr[i] = Wr2s[cur][kk][tmi+8*i]; wi[i] = Wi2s[cur][kk][tmi+8*i]; }
#pragma unroll
            for (int j = 0; j < 4; j++) { tr[j] = Trs[cur][kk][tni+16*j]; ti[j] = Tis[cur][kk][tni+16*j]; }
#pragma unroll
            for (int i = 0; i < 4; i++)
#pragma unroll
                for (int j = 0; j < 4; j++) {
                    accP[i][j] = fmaf(wr[i], tr[j], accP[i][j]);
                    accQ[i][j] = fmaf(wi[i], ti[j], accQ[i][j]);
                }
        }
        if (more) {
#pragma unroll
            for (int p = 0; p < 4; p++) { Wr2s[nxt][lak][lam+p*8] = ra[p].x; Wi2s[nxt][lak][lam+p*8] = ra[p].y; }
#pragma unroll
            for (int p = 0; p < 8; p++) { Trs[nxt][lbh+p*2][lbn] = rb[p].x; Tis[nxt][lbh+p*2][lbn] = rb[p].y; }
        }
        __syncthreads();
    }
#pragma unroll
    for (int i = 0; i < 4; i++)
#pragma unroll
        for (int j = 0; j < 4; j++) {
            int m   = bm + tmi + 8*i;
            int col = bn + tni + 16*j;
            int ip  = (m * OS + col) * C_CH + c;
            if (ip < OS*OS*C_CH) d_Pf[ip] = accP[i][j] - accQ[i][j];
            int mm = 320 - m;
            if (mm >= 192 && mm < 320) {
                int ipm = (mm * OS + col) * C_CH + c;
                d_Pf[ipm] = accP[i][j] + accQ[i][j];
            }
        }
}

// ---------------- Kaiser-Bessel i0 (Abramowitz & Stegun 9.8.1 / 9.8.2) --------
__device__ __forceinline__ float i0f(float x) {
    if (x < 3.75f) {
        float t = x * (1.0f / 3.75f);
        t *= t;
        return 1.0f + t*(3.5156229f + t*(3.0899424f + t*(1.2067492f +
                     t*(0.2659732f + t*(0.0360768f + t*0.0045813f)))));
    } else {
        float t = 3.75f / x;
        float p = 0.39894228f + t*(0.01328592f + t*(0.00225319f +
                  t*(-0.00157565f + t*(0.00916281f + t*(-0.02057706f +
                  t*(0.02635537f + t*(-0.01647633f + t*0.00392377f)))))));
        return expf(x) * rsqrtf(x) * p;
    }
}

// ---------------- KB interpolation: 6x6 gather, 8 real channels per point -----
__global__ void __launch_bounds__(256) interp_kernel(const float* __restrict__ trj,
                              float* __restrict__ out, float beta,
                              int out_floats) {
    int p = blockIdx.x * blockDim.x + threadIdx.x;
    if (p >= NPTS) return;
    float tx = trj[2*p], ty = trj[2*p + 1];
    float cx = __fadd_rn(__fmul_rn(tx, 1.25f), 160.0f);
    float cy = __fadd_rn(__fmul_rn(ty, 1.25f), 160.0f);
    float x0 = ceilf(cx - 3.0f);
    float y0 = ceilf(cy - 3.0f);

    float wx[6], wy[6];
    int   ox[6], oy[6];
#pragma unroll
    for (int d = 0; d < 6; d++) {
        float px = x0 + (float)d;
        float u  = (px - cx) / 3.0f;
        wx[d] = i0f(beta * sqrtf(fmaxf(1.0f - u*u, 0.0f)));
        int q = (int)px % OS; if (q < 0) q += OS;
        ox[d] = q * (OS * C_CH);

        float py = y0 + (float)d;
        u = (py - cy) / 3.0f;
        wy[d] = i0f(beta * sqrtf(fmaxf(1.0f - u*u, 0.0f)));
        q = (int)py % OS; if (q < 0) q += OS;
        oy[d] = q * C_CH;
    }

    float acc[8];
#pragma unroll
    for (int c = 0; c < 8; c++) acc[c] = 0.f;

#pragma unroll
    for (int dx = 0; dx < 6; dx++) {
#pragma unroll
        for (int dy = 0; dy < 6; dy++) {
            float w = wx[dx] * wy[dy];
            int base = min(ox[dx] + oy[dy], OS*OS*C_CH - 8);
            const float4* g = reinterpret_cast<const float4*>(&d_Pf[base]);
            float4 v0 = __ldg(g);
            float4 v1 = __ldg(g + 1);
            acc[0] = fmaf(w, v0.x, acc[0]);
            acc[1] = fmaf(w, v0.y, acc[1]);
            acc[2] = fmaf(w, v0.z, acc[2]);
            acc[3] = fmaf(w, v0.w, acc[3]);
            acc[4] = fmaf(w, v1.x, acc[4]);
            acc[5] = fmaf(w, v1.y, acc[5]);
            acc[6] = fmaf(w, v1.z, acc[6]);
            acc[7] = fmaf(w, v1.w, acc[7]);
        }
    }

    const float inv36 = 1.0f / 36.0f;
#pragma unroll
    for (int c = 0; c < 8; c++) {
        int idx = c * NPTS + p;
        if (idx < out_floats) out[idx] = acc[c] * inv36;
    }
}

// ---------------- launch -------------------------------------------------------
extern "C" void kernel_launch(void* const* d_in, const int* in_sizes, int n_in,
                              void* d_out, int out_size) {
    const float* img_r = (const float*)d_in[0];
    const float* img_i = (const float*)d_in[1];
    const float* trj   = (const float*)d_in[2];
    float* out = (float*)d_out;

    double beta_d = PI_F * sqrt(12.16);
    float beta  = (float)beta_d;
    float beta2 = (float)(beta_d * beta_d);

    build_all_w_kernel<<<(OS*OS + KFP*OS + 255) / 256, 256>>>();
    prep_kernel<<<(C_CH*NH*KFP + 255) / 256, 256>>>(img_r, img_i, beta2);

    dim3 g1(3, NH/32, C_CH);       // (3, 8, 8) = 192 blocks, col-pairs 0..191
    stage1_kernel<<<g1, 128>>>();
    dim3 g2(OS/64, 6, C_CH);       // (5, 6, 8) = 240 blocks, m=0..191
    stage2_kernel<<<g2, 128>>>();

    interp_kernel<<<(NPTS + 255) / 256, 256>>>(trj, out, beta, out_size);
}

// round 12
// speedup vs baseline: 1.4243x; 1.0864x over previous
#include <cuda_runtime.h>
#include <math.h>

#define C_CH 8
#define NH 256
#define NW 256
#define OS 320
#define PAD 32
#define KF 129
#define KFP 144
#define M2 192
#define NPTS (64*4096)
#define PI_F 3.14159265358979323846

// ---------------- scratch (static device arrays; no allocation) ----------------
__device__ float2 d_W1[KFP*OS];               // stage1 B: rows 32..160 of W, zero-pad
__device__ float2 d_W2[M2*KFP];               // stage2 A: W[m][32+hf], m<192, zero-pad hf>128
__device__ float2 d_S[C_CH*NH*KFP];           // folded input: A[j]+A[256-j]
__device__ float2 d_E[C_CH*NH*KFP];           // folded input: i*(A[j]-A[256-j])
__device__ float2 d_T[C_CH*NH*OS];            // after row transform (complex)
__device__ float2 d_Tf[C_CH*KFP*OS];          // K-folded T: (U, V)
__device__ __align__(16) float d_Pf[OS*OS*C_CH]; // re(spectrum), packed [y][x][c]

// ---------------- build W1 and W2 in one launch --------------------------------
__global__ void build_all_w_kernel() {
    int idx = blockIdx.x * blockDim.x + threadIdx.x;
    if (idx < KFP*OS) {
        int jf = idx / OS, k = idx % OS;
        if (jf > 128) { d_W1[idx] = make_float2(0.f, 0.f); return; }
        int row = 32 + jf;
        int r = (row * k) % OS;
        float s, c;
        sincospif(2.0f * (float)r / (float)OS, &s, &c);
        float sign = ((row + k) & 1) ? -1.0f : 1.0f;
        d_W1[idx] = make_float2(sign * c, -sign * s);
        return;
    }
    int i2 = idx - KFP*OS;
    if (i2 >= M2*KFP) return;
    int m = i2 / KFP, hf = i2 % KFP;
    if (hf > 128) { d_W2[i2] = make_float2(0.f, 0.f); return; }
    int col = 32 + hf;
    int r = (m * col) % OS;
    float s, c;
    sincospif(2.0f * (float)r / (float)OS, &s, &c);
    float sign = ((m + col) & 1) ? -1.0f : 1.0f;
    d_W2[i2] = make_float2(sign * c, -sign * s);
}

// ---------------- prep: apodize + scale + conjugate-pair fold ------------------
__global__ void prep_kernel(const float* __restrict__ img_r,
                            const float* __restrict__ img_i,
                            float beta2) {
    int idx = blockIdx.x * blockDim.x + threadIdx.x;
    if (idx >= C_CH*NH*KFP) return;
    int jf = idx % KFP;
    int h  = (idx / KFP) % NH;
    int c  = idx / (KFP * NH);
    if (jf > 128) { d_S[idx] = make_float2(0.f,0.f); d_E[idx] = make_float2(0.f,0.f); return; }
    float u, arg;
    u   = (float)PI_F * 6.0f * (float)(h - 128) / 320.0f;
    arg = sqrtf(beta2 - u*u);
    float fh = arg / sinhf(arg);
    u   = (float)PI_F * 6.0f * (float)(jf - 128) / 320.0f;
    arg = sqrtf(beta2 - u*u);
    float fj = arg / sinhf(arg);
    float s = fh * fj * (1.0f / 256.0f);

    int base = (c * NH + h) * NW;
    float ar = img_r[base + jf], ai = img_i[base + jf];
    float mr = 0.f, mi = 0.f;
    if (jf >= 1 && jf <= 127) {
        mr = img_r[base + 256 - jf];
        mi = img_i[base + 256 - jf];
    }
    float Sr = s * (ar + mr), Si = s * (ai + mi);
    float Dr = s * (ar - mr), Di = s * (ai - mi);
    d_S[idx] = make_float2(Sr, Si);
    d_E[idx] = make_float2(-Di, Dr);     // i*D
}

// ========== stage1: doubly-folded GEMM, col pairs, 32x(64 pair) tile ===========
__global__ void __launch_bounds__(128) stage1_kernel() {
    __shared__ float2 Ss[2][16][33];
    __shared__ float2 Es[2][16][33];
    __shared__ float2 Wv[2][16][64];   // (Wr, Wi)
    const int c = blockIdx.z;
    const float2* __restrict__ Sg = d_S + (size_t)c * NH * KFP;
    const float2* __restrict__ Eg = d_E + (size_t)c * NH * KFP;
    float2* __restrict__ Cm       = d_T + (size_t)c * NH * OS;

    const int tid = threadIdx.x;
    const int bm = blockIdx.y * 32;   // h rows
    const int bq = blockIdx.x * 64;   // col-pair base
    const int tmi = tid >> 4;
    const int tni = tid & 15;
    const int lak = tid & 15, lam = tid >> 4;
    const int lbn = tid & 63, lbh = tid >> 6;
    const int AMAX = NH*KFP - 1;
    const int BMAX = KFP*OS - 1;

    float2 P[4][4], Q[4][4];
#pragma unroll
    for (int i = 0; i < 4; i++)
#pragma unroll
        for (int j = 0; j < 4; j++) { P[i][j] = make_float2(0.f,0.f); Q[i][j] = make_float2(0.f,0.f); }

    float2 rs[4], re_[4], rw[8];
#pragma unroll
    for (int p = 0; p < 4; p++) {
        int ia = (bm + lam + p*8) * KFP + lak;
        rs[p]  = Sg[min(ia, AMAX)];
        re_[p] = Eg[min(ia, AMAX)];
    }
#pragma unroll
    for (int p = 0; p < 8; p++)
        rw[p] = d_W1[min((lbh + p*2) * OS + (bq + lbn), BMAX)];
#pragma unroll
    for (int p = 0; p < 4; p++) { Ss[0][lak][lam+p*8] = rs[p]; Es[0][lak][lam+p*8] = re_[p]; }
#pragma unroll
    for (int p = 0; p < 8; p++) Wv[0][lbh+p*2][lbn] = rw[p];
    __syncthreads();

    const int NT = KFP / 16;   // 9
    for (int t = 0; t < NT; t++) {
        const int cur = t & 1, nxt = cur ^ 1;
        const bool more = (t + 1 < NT);
        if (more) {
            int k0 = (t + 1) * 16;
#pragma unroll
            for (int p = 0; p < 4; p++) {
                int ia = (bm + lam + p*8) * KFP + (k0 + lak);
                rs[p]  = Sg[min(ia, AMAX)];
                re_[p] = Eg[min(ia, AMAX)];
            }
#pragma unroll
            for (int p = 0; p < 8; p++)
                rw[p] = d_W1[min((k0 + lbh + p*2) * OS + (bq + lbn), BMAX)];
        }
#pragma unroll
        for (int kk = 0; kk < 16; kk++) {
            float2 s[4], e[4], w[4];
#pragma unroll
            for (int i = 0; i < 4; i++) { s[i] = Ss[cur][kk][tmi+8*i]; e[i] = Es[cur][kk][tmi+8*i]; }
#pragma unroll
            for (int j = 0; j < 4; j++) w[j] = Wv[cur][kk][tni+16*j];
#pragma unroll
            for (int i = 0; i < 4; i++)
#pragma unroll
                for (int j = 0; j < 4; j++) {
                    P[i][j].x = fmaf(s[i].x, w[j].x, P[i][j].x);
                    P[i][j].y = fmaf(s[i].y, w[j].x, P[i][j].y);
                    Q[i][j].x = fmaf(e[i].x, w[j].y, Q[i][j].x);
                    Q[i][j].y = fmaf(e[i].y, w[j].y, Q[i][j].y);
                }
        }
        if (more) {
#pragma unroll
            for (int p = 0; p < 4; p++) { Ss[nxt][lak][lam+p*8] = rs[p]; Es[nxt][lak][lam+p*8] = re_[p]; }
#pragma unroll
            for (int p = 0; p < 8; p++) Wv[nxt][lbh+p*2][lbn] = rw[p];
        }
        __syncthreads();
    }
#pragma unroll
    for (int i = 0; i < 4; i++)
#pragma unroll
        for (int j = 0; j < 4; j++) {
            int row = bm + tmi + 8*i;
            int q   = bq + tni + 16*j;
            int ic  = row * OS + q;
            if (ic < NH*OS)
                Cm[ic] = make_float2(P[i][j].x + Q[i][j].x, P[i][j].y + Q[i][j].y);
            if (q >= 1 && q <= 128) {
                int icm = row * OS + (320 - q);
                Cm[icm] = make_float2(P[i][j].x - Q[i][j].x, P[i][j].y - Q[i][j].y);
            }
        }
}

// ---------------- fold T rows for stage2 K-fold --------------------------------
// Tf[hf][n] = (Tr[hf]+Tr[256-hf], Ti[hf]-Ti[256-hf]) for hf=1..127;
//             (Tr[hf], Ti[hf]) for hf=0,128; zeros hf>128
__global__ void fold_t_kernel() {
    int idx = blockIdx.x * blockDim.x + threadIdx.x;
    if (idx >= C_CH*KFP*OS) return;
    int n  = idx % OS;
    int hf = (idx / OS) % KFP;
    int c  = idx / (OS * KFP);
    if (hf > 128) { d_Tf[idx] = make_float2(0.f, 0.f); return; }
    const float2* T = d_T + (size_t)c * NH * OS;
    float2 a = T[hf * OS + n];
    if (hf >= 1 && hf <= 127) {
        float2 b = T[(256 - hf) * OS + n];
        d_Tf[idx] = make_float2(a.x + b.x, a.y - b.y);
    } else {
        d_Tf[idx] = a;
    }
}

// =================== stage2: doubly-folded real-part GEMM, fused pack ==========
// P = sum_hf Wr2[m][hf]*U[hf][n], Q = sum_hf Wi2[m][hf]*V[hf][n]   (K=144)
// re(G)[m] = P-Q (m=0..191); re(G)[320-m] = P+Q (written iff 320-m>=192)
__global__ void __launch_bounds__(128) stage2_kernel() {
    __shared__ float Wr2s[2][16][33];
    __shared__ float Wi2s[2][16][33];
    __shared__ float Trs[2][16][64];
    __shared__ float Tis[2][16][64];
    const int c = blockIdx.z;
    const float2* __restrict__ A = d_W2;                           // [m][hf], lda=KFP
    const float2* __restrict__ B = d_Tf + (size_t)c * KFP * OS;    // [hf][n]

    const int tid = threadIdx.x;
    const int bm = blockIdx.y * 32;   // m in [0,192)
    const int bn = blockIdx.x * 64;
    const int tmi = tid >> 4;
    const int tni = tid & 15;
    const int lak = tid & 15, lam = tid >> 4;
    const int lbn = tid & 63, lbh = tid >> 6;
    const int AMAX = M2*KFP - 1;
    const int BMAX = KFP*OS - 1;

    float accP[4][4], accQ[4][4];
#pragma unroll
    for (int i = 0; i < 4; i++)
#pragma unroll
        for (int j = 0; j < 4; j++) { accP[i][j] = 0.f; accQ[i][j] = 0.f; }

    float2 ra[4], rb[8];
#pragma unroll
    for (int p = 0; p < 4; p++)
        ra[p] = A[min((bm + lam + p*8) * KFP + lak, AMAX)];
#pragma unroll
    for (int p = 0; p < 8; p++)
        rb[p] = B[min((lbh + p*2) * OS + (bn + lbn), BMAX)];
#pragma unroll
    for (int p = 0; p < 4; p++) { Wr2s[0][lak][lam+p*8] = ra[p].x; Wi2s[0][lak][lam+p*8] = ra[p].y; }
#pragma unroll
    for (int p = 0; p < 8; p++) { Trs[0][lbh+p*2][lbn] = rb[p].x; Tis[0][lbh+p*2][lbn] = rb[p].y; }
    __syncthreads();

    const int NT = KFP / 16;   // 9
    for (int t = 0; t < NT; t++) {
        const int cur = t & 1, nxt = cur ^ 1;
        const bool more = (t + 1 < NT);
        if (more) {
            int k0 = (t + 1) * 16;
#pragma unroll
            for (int p = 0; p < 4; p++)
                ra[p] = A[min((bm + lam + p*8) * KFP + (k0 + lak), AMAX)];
#pragma unroll
            for (int p = 0; p < 8; p++)
                rb[p] = B[min((k0 + lbh + p*2) * OS + (bn + lbn), BMAX)];
        }
#pragma unroll
        for (int kk = 0; kk < 16; kk++) {
            float wr[4], wi[4], tr[4], ti[4];
#pragma unroll
            for (int i = 0; i < 4; i++) { wr[i] = Wr2s[cur][kk][tmi+8*i]; wi[i] = Wi2s[cur][kk][tmi+8*i]; }
#pragma unroll
            for (int j = 0; j < 4; j++) { tr[j] = Trs[cur][kk][tni+16*j]; ti[j] = Tis[cur][kk][tni+16*j]; }
#pragma unroll
            for (int i = 0; i < 4; i++)
#pragma unroll
                for (int j = 0; j < 4; j++) {
                    accP[i][j] = fmaf(wr[i], tr[j], accP[i][j]);
                    accQ[i][j] = fmaf(wi[i], ti[j], accQ[i][j]);
                }
        }
        if (more) {
#pragma unroll
            for (int p = 0; p < 4; p++) { Wr2s[nxt][lak][lam+p*8] = ra[p].x; Wi2s[nxt][lak][lam+p*8] = ra[p].y; }
#pragma unroll
            for (int p = 0; p < 8; p++) { Trs[nxt][lbh+p*2][lbn] = rb[p].x; Tis[nxt][lbh+p*2][lbn] = rb[p].y; }
        }
        __syncthreads();
    }
#pragma unroll
    for (int i = 0; i < 4; i++)
#pragma unroll
        for (int j = 0; j < 4; j++) {
            int m   = bm + tmi + 8*i;
            int col = bn + tni + 16*j;
            int ip  = (m * OS + col) * C_CH + c;
            if (ip < OS*OS*C_CH) d_Pf[ip] = accP[i][j] - accQ[i][j];
            int mm = 320 - m;
            if (mm >= 192 && mm < 320) {
                int ipm = (mm * OS + col) * C_CH + c;
                d_Pf[ipm] = accP[i][j] + accQ[i][j];
            }
        }
}

// ---------------- Kaiser-Bessel i0 (Abramowitz & Stegun 9.8.1 / 9.8.2) --------
__device__ __forceinline__ float i0f(float x) {
    if (x < 3.75f) {
        float t = x * (1.0f / 3.75f);
        t *= t;
        return 1.0f + t*(3.5156229f + t*(3.0899424f + t*(1.2067492f +
                     t*(0.2659732f + t*(0.0360768f + t*0.0045813f)))));
    } else {
        float t = 3.75f / x;
        float p = 0.39894228f + t*(0.01328592f + t*(0.00225319f +
                  t*(-0.00157565f + t*(0.00916281f + t*(-0.02057706f +
                  t*(0.02635537f + t*(-0.01647633f + t*0.00392377f)))))));
        return expf(x) * rsqrtf(x) * p;
    }
}

// ---------------- KB interpolation: 6x6 gather, 8 real channels per point -----
__global__ void __launch_bounds__(256) interp_kernel(const float* __restrict__ trj,
                              float* __restrict__ out, float beta,
                              int out_floats) {
    int p = blockIdx.x * blockDim.x + threadIdx.x;
    if (p >= NPTS) return;
    float tx = trj[2*p], ty = trj[2*p + 1];
    float cx = __fadd_rn(__fmul_rn(tx, 1.25f), 160.0f);
    float cy = __fadd_rn(__fmul_rn(ty, 1.25f), 160.0f);
    float x0 = ceilf(cx - 3.0f);
    float y0 = ceilf(cy - 3.0f);

    float wx[6], wy[6];
    int   ox[6], oy[6];
#pragma unroll
    for (int d = 0; d < 6; d++) {
        float px = x0 + (float)d;
        float u  = (px - cx) / 3.0f;
        wx[d] = i0f(beta * sqrtf(fmaxf(1.0f - u*u, 0.0f)));
        int q = (int)px % OS; if (q < 0) q += OS;
        ox[d] = q * (OS * C_CH);

        float py = y0 + (float)d;
        u = (py - cy) / 3.0f;
        wy[d] = i0f(beta * sqrtf(fmaxf(1.0f - u*u, 0.0f)));
        q = (int)py % OS; if (q < 0) q += OS;
        oy[d] = q * C_CH;
    }

    float acc[8];
#pragma unroll
    for (int c = 0; c < 8; c++) acc[c] = 0.f;

#pragma unroll
    for (int dx = 0; dx < 6; dx++) {
#pragma unroll
        for (int dy = 0; dy < 6; dy++) {
            float w = wx[dx] * wy[dy];
            int base = min(ox[dx] + oy[dy], OS*OS*C_CH - 8);
            const float4* g = reinterpret_cast<const float4*>(&d_Pf[base]);
            float4 v0 = __ldg(g);
            float4 v1 = __ldg(g + 1);
            acc[0] = fmaf(w, v0.x, acc[0]);
            acc[1] = fmaf(w, v0.y, acc[1]);
            acc[2] = fmaf(w, v0.z, acc[2]);
            acc[3] = fmaf(w, v0.w, acc[3]);
            acc[4] = fmaf(w, v1.x, acc[4]);
            acc[5] = fmaf(w, v1.y, acc[5]);
            acc[6] = fmaf(w, v1.z, acc[6]);
            acc[7] = fmaf(w, v1.w, acc[7]);
        }
    }

    const float inv36 = 1.0f / 36.0f;
#pragma unroll
    for (int c = 0; c < 8; c++) {
        int idx = c * NPTS + p;
        if (idx < out_floats) out[idx] = acc[c] * inv36;
    }
}

// ---------------- launch -------------------------------------------------------
extern "C" void kernel_launch(void* const* d_in, const int* in_sizes, int n_in,
                              void* d_out, int out_size) {
    const float* img_r = (const float*)d_in[0];
    const float* img_i = (const float*)d_in[1];
    const float* trj   = (const float*)d_in[2];
    float* out = (float*)d_out;

    double beta_d = PI_F * sqrt(12.16);
    float beta  = (float)beta_d;
    float beta2 = (float)(beta_d * beta_d);

    build_all_w_kernel<<<(KFP*OS + M2*KFP + 255) / 256, 256>>>();
    prep_kernel<<<(C_CH*NH*KFP + 255) / 256, 256>>>(img_r, img_i, beta2);

    dim3 g1(3, NH/32, C_CH);       // 192 blocks
    stage1_kernel<<<g1, 128>>>();
    fold_t_kernel<<<(C_CH*KFP*OS + 255) / 256, 256>>>();
    dim3 g2(OS/64, 6, C_CH);       // 240 blocks, m=0..191
    stage2_kernel<<<g2, 128>>>();

    interp_kernel<<<(NPTS + 255) / 256, 256>>>(trj, out, beta, out_size);
}

// round 13
// speedup vs baseline: 1.4370x; 1.0090x over previous
#include <cuda_runtime.h>
#include <math.h>

#define C_CH 8
#define NH 256
#define NW 256
#define OS 320
#define PAD 32
#define KF 129
#define KFP 144
#define MS 160           // rows per set in stage1 (129 padded to 5x32)
#define MR (2*MS)        // 320 stage1 rows total (U-set then V-set)
#define M2 192
#define NPTS (64*4096)
#define PI_F 3.14159265358979323846

// ---------------- scratch (static device arrays; no allocation) ----------------
__device__ float2 d_W1[KFP*OS];               // stage1 B: rows 32..160 of W, zero-pad
__device__ float2 d_W2[M2*KFP];               // stage2 A: W[m][32+hf], zero-pad hf>128
__device__ float  d_SX[C_CH*MR*KFP];          // stage1 A plane 1 (real)
__device__ float  d_EX[C_CH*MR*KFP];          // stage1 A plane 2 (real)
__device__ float  d_U[C_CH*KFP*OS];           // U = Re-folded transform rows
__device__ float  d_V[C_CH*KFP*OS];           // V = Im-folded transform rows
__device__ __align__(16) float d_Pf[OS*OS*C_CH]; // re(spectrum), packed [y][x][c]

// ---------------- build W1 and W2 in one launch --------------------------------
__global__ void build_all_w_kernel() {
    int idx = blockIdx.x * blockDim.x + threadIdx.x;
    if (idx < KFP*OS) {
        int jf = idx / OS, k = idx % OS;
        if (jf > 128) { d_W1[idx] = make_float2(0.f, 0.f); return; }
        int row = 32 + jf;
        int r = (row * k) % OS;
        float s, c;
        sincospif(2.0f * (float)r / (float)OS, &s, &c);
        float sign = ((row + k) & 1) ? -1.0f : 1.0f;
        d_W1[idx] = make_float2(sign * c, -sign * s);
        return;
    }
    int i2 = idx - KFP*OS;
    if (i2 >= M2*KFP) return;
    int m = i2 / KFP, hf = i2 % KFP;
    if (hf > 128) { d_W2[i2] = make_float2(0.f, 0.f); return; }
    int col = 32 + hf;
    int r = (m * col) % OS;
    float s, c;
    sincospif(2.0f * (float)r / (float)OS, &s, &c);
    float sign = ((m + col) & 1) ? -1.0f : 1.0f;
    d_W2[i2] = make_float2(sign * c, -sign * s);
}

// ---------------- prep: apodize + scale + fold in BOTH h and j -----------------
// U-set row hf (r<160):  SX = s*(ar(hf,jf)+ar(hf,jm)+ar(h',jf)+ar(h',jm))
//                        EX = -s*(ai(hf,jf)-ai(hf,jm)+ai(h',jf)-ai(h',jm))
// V-set row hf (r>=160): SX = s*(ai(hf,jf)+ai(hf,jm)-ai(h',jf)-ai(h',jm))
//                        EX = s*(ar(hf,jf)-ar(hf,jm)-ar(h',jf)+ar(h',jm))
// jm=256-jf (absent unless 1<=jf<=127); h'=256-hf (absent unless 1<=hf<=127)
__global__ void prep_kernel(const float* __restrict__ img_r,
                            const float* __restrict__ img_i,
                            float beta2) {
    int idx = blockIdx.x * blockDim.x + threadIdx.x;
    if (idx >= C_CH*MR*KFP) return;
    int jf = idx % KFP;
    int r  = (idx / KFP) % MR;
    int c  = idx / (KFP * MR);
    int set = r / MS;
    int hf  = r % MS;
    if (jf > 128 || hf > 128) { d_SX[idx] = 0.f; d_EX[idx] = 0.f; return; }
    float u, arg;
    u   = (float)PI_F * 6.0f * (float)(hf - 128) / 320.0f;
    arg = sqrtf(beta2 - u*u);
    float fh = arg / sinhf(arg);
    u   = (float)PI_F * 6.0f * (float)(jf - 128) / 320.0f;
    arg = sqrtf(beta2 - u*u);
    float fj = arg / sinhf(arg);
    float s = fh * fj * (1.0f / 256.0f);

    bool hasJm = (jf >= 1 && jf <= 127);
    bool hasHp = (hf >= 1 && hf <= 127);
    int b1 = (c * NH + hf) * NW;
    int b2 = (c * NH + (256 - hf)) * NW;
    int jm = 256 - jf;

    float ar1 = img_r[b1 + jf],            ai1 = img_i[b1 + jf];
    float am1 = hasJm ? img_r[b1 + jm] : 0.f, bm1 = hasJm ? img_i[b1 + jm] : 0.f;
    float ar2 = hasHp ? img_r[b2 + jf] : 0.f, ai2 = hasHp ? img_i[b2 + jf] : 0.f;
    float am2 = (hasHp && hasJm) ? img_r[b2 + jm] : 0.f;
    float bm2 = (hasHp && hasJm) ? img_i[b2 + jm] : 0.f;

    float sx, ex;
    if (set == 0) {
        sx =  s * (ar1 + am1 + ar2 + am2);
        ex = -s * (ai1 - bm1 + ai2 - bm2);
    } else {
        sx =  s * (ai1 + bm1 - ai2 - bm2);
        ex =  s * (ar1 - am1 - ar2 + am2);
    }
    d_SX[idx] = sx;
    d_EX[idx] = ex;
}

// ========== stage1: real GEMM with col-pair fold (M=320, N=192p, K=144) ========
// P = sum_jf SX*Wr1, Q = sum_jf EX*Wi1 ; out[q]=P+Q, out[320-q]=P-Q (q in [1,128])
// out = d_U for rows<160 (hf=row), d_V for rows>=160 (hf=row-160)
__global__ void __launch_bounds__(128) stage1_kernel() {
    __shared__ float SXs[2][16][33];
    __shared__ float EXs[2][16][33];
    __shared__ float2 Wv[2][16][64];
    const int c = blockIdx.z;
    const float* __restrict__ Sg = d_SX + (size_t)c * MR * KFP;
    const float* __restrict__ Eg = d_EX + (size_t)c * MR * KFP;

    const int tid = threadIdx.x;
    const int bm = blockIdx.y * 32;   // row base (0..288), blocks never straddle sets
    const int bq = blockIdx.x * 64;   // col-pair base
    const int tmi = tid >> 4;
    const int tni = tid & 15;
    const int lak = tid & 15, lam = tid >> 4;
    const int lbn = tid & 63, lbh = tid >> 6;
    const int AMAX = MR*KFP - 1;
    const int BMAX = KFP*OS - 1;

    float P[4][4], Q[4][4];
#pragma unroll
    for (int i = 0; i < 4; i++)
#pragma unroll
        for (int j = 0; j < 4; j++) { P[i][j] = 0.f; Q[i][j] = 0.f; }

    float rs[4], re_[4];
    float2 rw[8];
#pragma unroll
    for (int p = 0; p < 4; p++) {
        int ia = (bm + lam + p*8) * KFP + lak;
        rs[p]  = Sg[min(ia, AMAX)];
        re_[p] = Eg[min(ia, AMAX)];
    }
#pragma unroll
    for (int p = 0; p < 8; p++)
        rw[p] = d_W1[min((lbh + p*2) * OS + (bq + lbn), BMAX)];
#pragma unroll
    for (int p = 0; p < 4; p++) { SXs[0][lak][lam+p*8] = rs[p]; EXs[0][lak][lam+p*8] = re_[p]; }
#pragma unroll
    for (int p = 0; p < 8; p++) Wv[0][lbh+p*2][lbn] = rw[p];
    __syncthreads();

    const int NT = KFP / 16;   // 9
    for (int t = 0; t < NT; t++) {
        const int cur = t & 1, nxt = cur ^ 1;
        const bool more = (t + 1 < NT);
        if (more) {
            int k0 = (t + 1) * 16;
#pragma unroll
            for (int p = 0; p < 4; p++) {
                int ia = (bm + lam + p*8) * KFP + (k0 + lak);
                rs[p]  = Sg[min(ia, AMAX)];
                re_[p] = Eg[min(ia, AMAX)];
            }
#pragma unroll
            for (int p = 0; p < 8; p++)
                rw[p] = d_W1[min((k0 + lbh + p*2) * OS + (bq + lbn), BMAX)];
        }
#pragma unroll
        for (int kk = 0; kk < 16; kk++) {
            float sx[4], ex[4];
            float2 w[4];
#pragma unroll
            for (int i = 0; i < 4; i++) { sx[i] = SXs[cur][kk][tmi+8*i]; ex[i] = EXs[cur][kk][tmi+8*i]; }
#pragma unroll
            for (int j = 0; j < 4; j++) w[j] = Wv[cur][kk][tni+16*j];
#pragma unroll
            for (int i = 0; i < 4; i++)
#pragma unroll
                for (int j = 0; j < 4; j++) {
                    P[i][j] = fmaf(sx[i], w[j].x, P[i][j]);
                    Q[i][j] = fmaf(ex[i], w[j].y, Q[i][j]);
                }
        }
        if (more) {
#pragma unroll
            for (int p = 0; p < 4; p++) { SXs[nxt][lak][lam+p*8] = rs[p]; EXs[nxt][lak][lam+p*8] = re_[p]; }
#pragma unroll
            for (int p = 0; p < 8; p++) Wv[nxt][lbh+p*2][lbn] = rw[p];
        }
        __syncthreads();
    }

    const int set = (bm >= MS) ? 1 : 0;
    float* __restrict__ Og = (set ? d_V : d_U) + (size_t)c * KFP * OS;
#pragma unroll
    for (int i = 0; i < 4; i++)
#pragma unroll
        for (int j = 0; j < 4; j++) {
            int row = bm + tmi + 8*i;
            int hf  = row - set * MS;
            if (hf >= KFP) continue;
            int q = bq + tni + 16*j;
            Og[hf * OS + q] = P[i][j] + Q[i][j];
            if (q >= 1 && q <= 128)
                Og[hf * OS + (320 - q)] = P[i][j] - Q[i][j];
        }
}

// =================== stage2: doubly-folded real-part GEMM, fused pack ==========
// P = sum_hf Wr2[m][hf]*U[hf][n], Q = sum_hf Wi2[m][hf]*V[hf][n]   (K=144)
// re(G)[m] = P-Q (m=0..191); re(G)[320-m] = P+Q (written iff 320-m>=192)
__global__ void __launch_bounds__(128) stage2_kernel() {
    __shared__ float Wr2s[2][16][33];
    __shared__ float Wi2s[2][16][33];
    __shared__ float Trs[2][16][64];
    __shared__ float Tis[2][16][64];
    const int c = blockIdx.z;
    const float2* __restrict__ A = d_W2;                        // [m][hf], lda=KFP
    const float*  __restrict__ BU = d_U + (size_t)c * KFP * OS; // [hf][n]
    const float*  __restrict__ BV = d_V + (size_t)c * KFP * OS;

    const int tid = threadIdx.x;
    const int bm = blockIdx.y * 32;   // m in [0,192)
    const int bn = blockIdx.x * 64;
    const int tmi = tid >> 4;
    const int tni = tid & 15;
    const int lak = tid & 15, lam = tid >> 4;
    const int lbn = tid & 63, lbh = tid >> 6;
    const int AMAX = M2*KFP - 1;
    const int BMAX = KFP*OS - 1;

    float accP[4][4], accQ[4][4];
#pragma unroll
    for (int i = 0; i < 4; i++)
#pragma unroll
        for (int j = 0; j < 4; j++) { accP[i][j] = 0.f; accQ[i][j] = 0.f; }

    float2 ra[4];
    float rbu[8], rbv[8];
#pragma unroll
    for (int p = 0; p < 4; p++)
        ra[p] = A[min((bm + lam + p*8) * KFP + lak, AMAX)];
#pragma unroll
    for (int p = 0; p < 8; p++) {
        int ib = min((lbh + p*2) * OS + (bn + lbn), BMAX);
        rbu[p] = BU[ib];
        rbv[p] = BV[ib];
    }
#pragma unroll
    for (int p = 0; p < 4; p++) { Wr2s[0][lak][lam+p*8] = ra[p].x; Wi2s[0][lak][lam+p*8] = ra[p].y; }
#pragma unroll
    for (int p = 0; p < 8; p++) { Trs[0][lbh+p*2][lbn] = rbu[p]; Tis[0][lbh+p*2][lbn] = rbv[p]; }
    __syncthreads();

    const int NT = KFP / 16;   // 9
    for (int t = 0; t < NT; t++) {
        const int cur = t & 1, nxt = cur ^ 1;
        const bool more = (t + 1 < NT);
        if (more) {
            int k0 = (t + 1) * 16;
#pragma unroll
            for (int p = 0; p < 4; p++)
                ra[p] = A[min((bm + lam + p*8) * KFP + (k0 + lak), AMAX)];
#pragma unroll
            for (int p = 0; p < 8; p++) {
                int ib = min((k0 + lbh + p*2) * OS + (bn + lbn), BMAX);
                rbu[p] = BU[ib];
                rbv[p] = BV[ib];
            }
        }
#pragma unroll
        for (int kk = 0; kk < 16; kk++) {
            float wr[4], wi[4], tr[4], ti[4];
#pragma unroll
            for (int i = 0; i < 4; i++) { wr[i] = Wr2s[cur][kk][tmi+8*i]; wi[i] = Wi2s[cur][kk][tmi+8*i]; }
#pragma unroll
            for (int j = 0; j < 4; j++) { tr[j] = Trs[cur][kk][tni+16*j]; ti[j] = Tis[cur][kk][tni+16*j]; }
#pragma unroll
            for (int i = 0; i < 4; i++)
#pragma unroll
                for (int j = 0; j < 4; j++) {
                    accP[i][j] = fmaf(wr[i], tr[j], accP[i][j]);
                    accQ[i][j] = fmaf(wi[i], ti[j], accQ[i][j]);
                }
        }
        if (more) {
#pragma unroll
            for (int p = 0; p < 4; p++) { Wr2s[nxt][lak][lam+p*8] = ra[p].x; Wi2s[nxt][lak][lam+p*8] = ra[p].y; }
#pragma unroll
            for (int p = 0; p < 8; p++) { Trs[nxt][lbh+p*2][lbn] = rbu[p]; Tis[nxt][lbh+p*2][lbn] = rbv[p]; }
        }
        __syncthreads();
    }
#pragma unroll
    for (int i = 0; i < 4; i++)
#pragma unroll
        for (int j = 0; j < 4; j++) {
            int m   = bm + tmi + 8*i;
            int col = bn + tni + 16*j;
            int ip  = (m * OS + col) * C_CH + c;
            if (ip < OS*OS*C_CH) d_Pf[ip] = accP[i][j] - accQ[i][j];
            int mm = 320 - m;
            if (mm >= 192 && mm < 320) {
                int ipm = (mm * OS + col) * C_CH + c;
                d_Pf[ipm] = accP[i][j] + accQ[i][j];
            }
        }
}

// ---------------- Kaiser-Bessel i0 (Abramowitz & Stegun 9.8.1 / 9.8.2) --------
__device__ __forceinline__ float i0f(float x) {
    if (x < 3.75f) {
        float t = x * (1.0f / 3.75f);
        t *= t;
        return 1.0f + t*(3.5156229f + t*(3.0899424f + t*(1.2067492f +
                     t*(0.2659732f + t*(0.0360768f + t*0.0045813f)))));
    } else {
        float t = 3.75f / x;
        float p = 0.39894228f + t*(0.01328592f + t*(0.00225319f +
                  t*(-0.00157565f + t*(0.00916281f + t*(-0.02057706f +
                  t*(0.02635537f + t*(-0.01647633f + t*0.00392377f)))))));
        return expf(x) * rsqrtf(x) * p;
    }
}

// ---------------- KB interpolation: 6x6 gather, 8 real channels per point -----
__global__ void __launch_bounds__(256) interp_kernel(const float* __restrict__ trj,
                              float* __restrict__ out, float beta,
                              int out_floats) {
    int p = blockIdx.x * blockDim.x + threadIdx.x;
    if (p >= NPTS) return;
    float tx = trj[2*p], ty = trj[2*p + 1];
    float cx = __fadd_rn(__fmul_rn(tx, 1.25f), 160.0f);
    float cy = __fadd_rn(__fmul_rn(ty, 1.25f), 160.0f);
    float x0 = ceilf(cx - 3.0f);
    float y0 = ceilf(cy - 3.0f);

    float wx[6], wy[6];
    int   ox[6], oy[6];
#pragma unroll
    for (int d = 0; d < 6; d++) {
        float px = x0 + (float)d;
        float u  = (px - cx) / 3.0f;
        wx[d] = i0f(beta * sqrtf(fmaxf(1.0f - u*u, 0.0f)));
        int q = (int)px % OS; if (q < 0) q += OS;
        ox[d] = q * (OS * C_CH);

        float py = y0 + (float)d;
        u = (py - cy) / 3.0f;
        wy[d] = i0f(beta * sqrtf(fmaxf(1.0f - u*u, 0.0f)));
        q = (int)py % OS; if (q < 0) q += OS;
        oy[d] = q * C_CH;
    }

    float acc[8];
#pragma unroll
    for (int c = 0; c < 8; c++) acc[c] = 0.f;

#pragma unroll
    for (int dx = 0; dx < 6; dx++) {
#pragma unroll
        for (int dy = 0; dy < 6; dy++) {
            float w = wx[dx] * wy[dy];
            int base = min(ox[dx] + oy[dy], OS*OS*C_CH - 8);
            const float4* g = reinterpret_cast<const float4*>(&d_Pf[base]);
            float4 v0 = __ldg(g);
            float4 v1 = __ldg(g + 1);
            acc[0] = fmaf(w, v0.x, acc[0]);
            acc[1] = fmaf(w, v0.y, acc[1]);
            acc[2] = fmaf(w, v0.z, acc[2]);
            acc[3] = fmaf(w, v0.w, acc[3]);
            acc[4] = fmaf(w, v1.x, acc[4]);
            acc[5] = fmaf(w, v1.y, acc[5]);
            acc[6] = fmaf(w, v1.z, acc[6]);
            acc[7] = fmaf(w, v1.w, acc[7]);
        }
    }

    const float inv36 = 1.0f / 36.0f;
#pragma unroll
    for (int c = 0; c < 8; c++) {
        int idx = c * NPTS + p;
        if (idx < out_floats) out[idx] = acc[c] * inv36;
    }
}

// ---------------- launch -------------------------------------------------------
extern "C" void kernel_launch(void* const* d_in, const int* in_sizes, int n_in,
                              void* d_out, int out_size) {
    const float* img_r = (const float*)d_in[0];
    const float* img_i = (const float*)d_in[1];
    const float* trj   = (const float*)d_in[2];
    float* out = (float*)d_out;

    double beta_d = PI_F * sqrt(12.16);
    float beta  = (float)beta_d;
    float beta2 = (float)(beta_d * beta_d);

    build_all_w_kernel<<<(KFP*OS + M2*KFP + 255) / 256, 256>>>();
    prep_kernel<<<(C_CH*MR*KFP + 255) / 256, 256>>>(img_r, img_i, beta2);

    dim3 g1(3, MR/32, C_CH);       // (3, 10, 8) = 240 blocks
    stage1_kernel<<<g1, 128>>>();
    dim3 g2(OS/64, 6, C_CH);       // (5, 6, 8) = 240 blocks, m=0..191
    stage2_kernel<<<g2, 128>>>();

    interp_kernel<<<(NPTS + 255) / 256, 256>>>(trj, out, beta, out_size);
}

// round 16
// speedup vs baseline: 1.6413x; 1.1422x over previous
#include <cuda_runtime.h>
#include <cuda_fp16.h>
#include <math.h>

#define C_CH 8
#define NH 256
#define NW 256
#define OS 320
#define KF 129
#define KFP 144
#define MS 160           // rows per set in stage1 (129 padded to 5x32)
#define MR (2*MS)        // 320 stage1 rows total (U-set then V-set)
#define M2 192
#define NPTS (64*4096)
#define PI_F 3.14159265358979323846
#define GRID_SCALE 16384.0f          // 2^14: lifts fp16 grid out of subnormals
#define INV_W (1.0f / 768.0f)        // 1/(6*128); (1/768)^2 = 1/(36*2^14)

// ---------------- scratch (static device arrays; no allocation) ----------------
__device__ float2 d_W1[KFP*OS];               // stage1 B: rows 32..160 of W, zero-pad
__device__ float2 d_W2[M2*KFP];               // stage2 A: W[m][32+hf], zero-pad hf>128
__device__ float  d_SX[C_CH*MR*KFP];          // stage1 A plane 1 (real)
__device__ float  d_EX[C_CH*MR*KFP];          // stage1 A plane 2 (real)
__device__ float  d_U[C_CH*KFP*OS];           // U = Re-folded transform rows
__device__ float  d_V[C_CH*KFP*OS];           // V = Im-folded transform rows
__device__ __align__(16) float  d_Pf[OS*OS*C_CH]; // re(spectrum) fp32, [y][x][c]
__device__ __align__(16) __half d_Ph[OS*OS*C_CH]; // re(spectrum) fp16 (x2^14), [y][x][c]

// ---------------- setup: W1 + W2 + prep fold, one launch ----------------------
__global__ void setup_kernel(const float* __restrict__ img_r,
                             const float* __restrict__ img_i,
                             float beta2) {
    int idx = blockIdx.x * blockDim.x + threadIdx.x;
    if (idx < KFP*OS) {
        int jf = idx / OS, k = idx % OS;
        if (jf > 128) { d_W1[idx] = make_float2(0.f, 0.f); return; }
        int row = 32 + jf;
        int r = (row * k) % OS;
        float s, c;
        sincospif(2.0f * (float)r / (float)OS, &s, &c);
        float sign = ((row + k) & 1) ? -1.0f : 1.0f;
        d_W1[idx] = make_float2(sign * c, -sign * s);
        return;
    }
    idx -= KFP*OS;
    if (idx < M2*KFP) {
        int m = idx / KFP, hf = idx % KFP;
        if (hf > 128) { d_W2[idx] = make_float2(0.f, 0.f); return; }
        int col = 32 + hf;
        int r = (m * col) % OS;
        float s, c;
        sincospif(2.0f * (float)r / (float)OS, &s, &c);
        float sign = ((m + col) & 1) ? -1.0f : 1.0f;
        d_W2[idx] = make_float2(sign * c, -sign * s);
        return;
    }
    idx -= M2*KFP;
    if (idx >= C_CH*MR*KFP) return;
    // ---- prep: apodize + scale + fold in BOTH h and j ----
    int jf = idx % KFP;
    int r  = (idx / KFP) % MR;
    int c  = idx / (KFP * MR);
    int set = r / MS;
    int hf  = r % MS;
    if (jf > 128 || hf > 128) { d_SX[idx] = 0.f; d_EX[idx] = 0.f; return; }
    float u, arg;
    u   = (float)PI_F * 6.0f * (float)(hf - 128) / 320.0f;
    arg = sqrtf(beta2 - u*u);
    float fh = arg / sinhf(arg);
    u   = (float)PI_F * 6.0f * (float)(jf - 128) / 320.0f;
    arg = sqrtf(beta2 - u*u);
    float fj = arg / sinhf(arg);
    float s = fh * fj * (1.0f / 256.0f);

    bool hasJm = (jf >= 1 && jf <= 127);
    bool hasHp = (hf >= 1 && hf <= 127);
    int b1 = (c * NH + hf) * NW;
    int b2 = (c * NH + (256 - hf)) * NW;
    int jm = 256 - jf;

    float ar1 = img_r[b1 + jf],              ai1 = img_i[b1 + jf];
    float am1 = hasJm ? img_r[b1 + jm] : 0.f, bm1 = hasJm ? img_i[b1 + jm] : 0.f;
    float ar2 = hasHp ? img_r[b2 + jf] : 0.f, ai2 = hasHp ? img_i[b2 + jf] : 0.f;
    float am2 = (hasHp && hasJm) ? img_r[b2 + jm] : 0.f;
    float bm2 = (hasHp && hasJm) ? img_i[b2 + jm] : 0.f;

    float sx, ex;
    if (set == 0) {
        sx =  s * (ar1 + am1 + ar2 + am2);
        ex = -s * (ai1 - bm1 + ai2 - bm2);
    } else {
        sx =  s * (ai1 + bm1 - ai2 - bm2);
        ex =  s * (ar1 - am1 - ar2 + am2);
    }
    d_SX[idx] = sx;
    d_EX[idx] = ex;
}

// ========== stage1: real GEMM with col-pair fold (M=320, N=192p, K=144) ========
__global__ void __launch_bounds__(128) stage1_kernel() {
    __shared__ float SXs[2][16][33];
    __shared__ float EXs[2][16][33];
    __shared__ float2 Wv[2][16][64];
    const int c = blockIdx.z;
    const float* __restrict__ Sg = d_SX + (size_t)c * MR * KFP;
    const float* __restrict__ Eg = d_EX + (size_t)c * MR * KFP;

    const int tid = threadIdx.x;
    const int bm = blockIdx.y * 32;
    const int bq = blockIdx.x * 64;
    const int tmi = tid >> 4;
    const int tni = tid & 15;
    const int lak = tid & 15, lam = tid >> 4;
    const int lbn = tid & 63, lbh = tid >> 6;
    const int AMAX = MR*KFP - 1;
    const int BMAX = KFP*OS - 1;

    float P[4][4], Q[4][4];
#pragma unroll
    for (int i = 0; i < 4; i++)
#pragma unroll
        for (int j = 0; j < 4; j++) { P[i][j] = 0.f; Q[i][j] = 0.f; }

    float rs[4], re_[4];
    float2 rw[8];
#pragma unroll
    for (int p = 0; p < 4; p++) {
        int ia = (bm + lam + p*8) * KFP + lak;
        rs[p]  = Sg[min(ia, AMAX)];
        re_[p] = Eg[min(ia, AMAX)];
    }
#pragma unroll
    for (int p = 0; p < 8; p++)
        rw[p] = d_W1[min((lbh + p*2) * OS + (bq + lbn), BMAX)];
#pragma unroll
    for (int p = 0; p < 4; p++) { SXs[0][lak][lam+p*8] = rs[p]; EXs[0][lak][lam+p*8] = re_[p]; }
#pragma unroll
    for (int p = 0; p < 8; p++) Wv[0][lbh+p*2][lbn] = rw[p];
    __syncthreads();

    const int NT = KFP / 16;   // 9
    for (int t = 0; t < NT; t++) {
        const int cur = t & 1, nxt = cur ^ 1;
        const bool more = (t + 1 < NT);
        if (more) {
            int k0 = (t + 1) * 16;
#pragma unroll
            for (int p = 0; p < 4; p++) {
                int ia = (bm + lam + p*8) * KFP + (k0 + lak);
                rs[p]  = Sg[min(ia, AMAX)];
                re_[p] = Eg[min(ia, AMAX)];
            }
#pragma unroll
            for (int p = 0; p < 8; p++)
                rw[p] = d_W1[min((k0 + lbh + p*2) * OS + (bq + lbn), BMAX)];
        }
#pragma unroll
        for (int kk = 0; kk < 16; kk++) {
            float sx[4], ex[4];
            float2 w[4];
#pragma unroll
            for (int i = 0; i < 4; i++) { sx[i] = SXs[cur][kk][tmi+8*i]; ex[i] = EXs[cur][kk][tmi+8*i]; }
#pragma unroll
            for (int j = 0; j < 4; j++) w[j] = Wv[cur][kk][tni+16*j];
#pragma unroll
            for (int i = 0; i < 4; i++)
#pragma unroll
                for (int j = 0; j < 4; j++) {
                    P[i][j] = fmaf(sx[i], w[j].x, P[i][j]);
                    Q[i][j] = fmaf(ex[i], w[j].y, Q[i][j]);
                }
        }
        if (more) {
#pragma unroll
            for (int p = 0; p < 4; p++) { SXs[nxt][lak][lam+p*8] = rs[p]; EXs[nxt][lak][lam+p*8] = re_[p]; }
#pragma unroll
            for (int p = 0; p < 8; p++) Wv[nxt][lbh+p*2][lbn] = rw[p];
        }
        __syncthreads();
    }

    const int set = (bm >= MS) ? 1 : 0;
    float* __restrict__ Og = (set ? d_V : d_U) + (size_t)c * KFP * OS;
#pragma unroll
    for (int i = 0; i < 4; i++)
#pragma unroll
        for (int j = 0; j < 4; j++) {
            int row = bm + tmi + 8*i;
            int hf  = row - set * MS;
            if (hf >= KFP) continue;
            int q = bq + tni + 16*j;
            Og[hf * OS + q] = P[i][j] + Q[i][j];
            if (q >= 1 && q <= 128)
                Og[hf * OS + (320 - q)] = P[i][j] - Q[i][j];
        }
}

// =================== stage2: doubly-folded real-part GEMM -> fp32 + fp16 pack ==
__global__ void __launch_bounds__(128) stage2_kernel() {
    __shared__ float Wr2s[2][16][33];
    __shared__ float Wi2s[2][16][33];
    __shared__ float Trs[2][16][64];
    __shared__ float Tis[2][16][64];
    const int c = blockIdx.z;
    const float2* __restrict__ A = d_W2;
    const float*  __restrict__ BU = d_U + (size_t)c * KFP * OS;
    const float*  __restrict__ BV = d_V + (size_t)c * KFP * OS;

    const int tid = threadIdx.x;
    const int bm = blockIdx.y * 32;   // m in [0,192)
    const int bn = blockIdx.x * 64;
    const int tmi = tid >> 4;
    const int tni = tid & 15;
    const int lak = tid & 15, lam = tid >> 4;
    const int lbn = tid & 63, lbh = tid >> 6;
    const int AMAX = M2*KFP - 1;
    const int BMAX = KFP*OS - 1;

    float accP[4][4], accQ[4][4];
#pragma unroll
    for (int i = 0; i < 4; i++)
#pragma unroll
        for (int j = 0; j < 4; j++) { accP[i][j] = 0.f; accQ[i][j] = 0.f; }

    float2 ra[4];
    float rbu[8], rbv[8];
#pragma unroll
    for (int p = 0; p < 4; p++)
        ra[p] = A[min((bm + lam + p*8) * KFP + lak, AMAX)];
#pragma unroll
    for (int p = 0; p < 8; p++) {
        int ib = min((lbh + p*2) * OS + (bn + lbn), BMAX);
        rbu[p] = BU[ib];
        rbv[p] = BV[ib];
    }
#pragma unroll
    for (int p = 0; p < 4; p++) { Wr2s[0][lak][lam+p*8] = ra[p].x; Wi2s[0][lak][lam+p*8] = ra[p].y; }
#pragma unroll
    for (int p = 0; p < 8; p++) { Trs[0][lbh+p*2][lbn] = rbu[p]; Tis[0][lbh+p*2][lbn] = rbv[p]; }
    __syncthreads();

    const int NT = KFP / 16;   // 9
    for (int t = 0; t < NT; t++) {
        const int cur = t & 1, nxt = cur ^ 1;
        const bool more = (t + 1 < NT);
        if (more) {
            int k0 = (t + 1) * 16;
#pragma unroll
            for (int p = 0; p < 4; p++)
                ra[p] = A[min((bm + lam + p*8) * KFP + (k0 + lak), AMAX)];
#pragma unroll
            for (int p = 0; p < 8; p++) {
                int ib = min((k0 + lbh + p*2) * OS + (bn + lbn), BMAX);
                rbu[p] = BU[ib];
                rbv[p] = BV[ib];
            }
        }
#pragma unroll
        for (int kk = 0; kk < 16; kk++) {
            float wr[4], wi[4], tr[4], ti[4];
#pragma unroll
            for (int i = 0; i < 4; i++) { wr[i] = Wr2s[cur][kk][tmi+8*i]; wi[i] = Wi2s[cur][kk][tmi+8*i]; }
#pragma unroll
            for (int j = 0; j < 4; j++) { tr[j] = Trs[cur][kk][tni+16*j]; ti[j] = Tis[cur][kk][tni+16*j]; }
#pragma unroll
            for (int i = 0; i < 4; i++)
#pragma unroll
                for (int j = 0; j < 4; j++) {
                    accP[i][j] = fmaf(wr[i], tr[j], accP[i][j]);
                    accQ[i][j] = fmaf(wi[i], ti[j], accQ[i][j]);
                }
        }
        if (more) {
#pragma unroll
            for (int p = 0; p < 4; p++) { Wr2s[nxt][lak][lam+p*8] = ra[p].x; Wi2s[nxt][lak][lam+p*8] = ra[p].y; }
#pragma unroll
            for (int p = 0; p < 8; p++) { Trs[nxt][lbh+p*2][lbn] = rbu[p]; Tis[nxt][lbh+p*2][lbn] = rbv[p]; }
        }
        __syncthreads();
    }
#pragma unroll
    for (int i = 0; i < 4; i++)
#pragma unroll
        for (int j = 0; j < 4; j++) {
            int m   = bm + tmi + 8*i;
            int col = bn + tni + 16*j;
            float gv = accP[i][j] - accQ[i][j];
            int ip  = (m * OS + col) * C_CH + c;
            if (ip < OS*OS*C_CH) {
                d_Pf[ip] = gv;
                d_Ph[ip] = __float2half_rn(gv * GRID_SCALE);
            }
            int mm = 320 - m;
            if (mm >= 192 && mm < 320) {
                float gv2 = accP[i][j] + accQ[i][j];
                int ipm = (mm * OS + col) * C_CH + c;
                d_Pf[ipm] = gv2;
                d_Ph[ipm] = __float2half_rn(gv2 * GRID_SCALE);
            }
        }
}

// ---------------- Kaiser-Bessel i0 (Abramowitz & Stegun 9.8.1 / 9.8.2) --------
__device__ __forceinline__ float i0f(float x) {
    if (x < 3.75f) {
        float t = x * (1.0f / 3.75f);
        t *= t;
        return 1.0f + t*(3.5156229f + t*(3.0899424f + t*(1.2067492f +
                     t*(0.2659732f + t*(0.0360768f + t*0.0045813f)))));
    } else {
        float t = 3.75f / x;
        float p = 0.39894228f + t*(0.01328592f + t*(0.00225319f +
                  t*(-0.00157565f + t*(0.00916281f + t*(-0.02057706f +
                  t*(0.02635537f + t*(-0.01647633f + t*0.00392377f)))))));
        return expf(x) * rsqrtf(x) * p;
    }
}

// ---------------- KB interpolation: mixed-precision 6x6 gather -----------------
// Central 4x4 taps (dx,dy in [1,4]): fp32 grid (2x LDG.128).
// Ring taps (20): fp16 grid (1x LDG.128). Ring carries ~0.03% of sum(w^2).
__global__ void __launch_bounds__(256) interp_kernel(const float* __restrict__ trj,
                              float* __restrict__ out, float beta,
                              int out_floats) {
    int p = blockIdx.x * blockDim.x + threadIdx.x;
    if (p >= NPTS) return;
    float tx = trj[2*p], ty = trj[2*p + 1];
    float cx = __fadd_rn(__fmul_rn(tx, 1.25f), 160.0f);
    float cy = __fadd_rn(__fmul_rn(ty, 1.25f), 160.0f);
    float x0 = ceilf(cx - 3.0f);
    float y0 = ceilf(cy - 3.0f);

    float wx[6], wy[6];
    int   ox[6], oy[6];
#pragma unroll
    for (int d = 0; d < 6; d++) {
        float px = x0 + (float)d;
        float u  = (px - cx) / 3.0f;
        wx[d] = i0f(beta * sqrtf(fmaxf(1.0f - u*u, 0.0f))) * INV_W;
        int q = (int)px % OS; if (q < 0) q += OS;
        ox[d] = q * (OS * C_CH);

        float py = y0 + (float)d;
        u = (py - cy) / 3.0f;
        wy[d] = i0f(beta * sqrtf(fmaxf(1.0f - u*u, 0.0f))) * INV_W;
        int q2 = (int)py % OS; if (q2 < 0) q2 += OS;
        oy[d] = q2 * C_CH;
    }

    float acc[8];
#pragma unroll
    for (int c = 0; c < 8; c++) acc[c] = 0.f;

#pragma unroll
    for (int dx = 0; dx < 6; dx++) {
#pragma unroll
        for (int dy = 0; dy < 6; dy++) {
            float w = wx[dx] * wy[dy];
            int base = min(ox[dx] + oy[dy], OS*OS*C_CH - 8);
            if (dx >= 1 && dx <= 4 && dy >= 1 && dy <= 4) {
                // fp32 grid; weights were scaled by 1/(36*2^14) -> restore 2^14
                float wf = w * GRID_SCALE;
                const float4* g = reinterpret_cast<const float4*>(&d_Pf[base]);
                float4 v0 = __ldg(g);
                float4 v1 = __ldg(g + 1);
                acc[0] = fmaf(wf, v0.x, acc[0]);
                acc[1] = fmaf(wf, v0.y, acc[1]);
                acc[2] = fmaf(wf, v0.z, acc[2]);
                acc[3] = fmaf(wf, v0.w, acc[3]);
                acc[4] = fmaf(wf, v1.x, acc[4]);
                acc[5] = fmaf(wf, v1.y, acc[5]);
                acc[6] = fmaf(wf, v1.z, acc[6]);
                acc[7] = fmaf(wf, v1.w, acc[7]);
            } else {
                // fp16 grid already carries the 2^14 scale
                uint4 v = __ldg(reinterpret_cast<const uint4*>(&d_Ph[base]));
                float2 f0 = __half22float2(*reinterpret_cast<const __half2*>(&v.x));
                float2 f1 = __half22float2(*reinterpret_cast<const __half2*>(&v.y));
                float2 f2 = __half22float2(*reinterpret_cast<const __half2*>(&v.z));
                float2 f3 = __half22float2(*reinterpret_cast<const __half2*>(&v.w));
                acc[0] = fmaf(w, f0.x, acc[0]);
                acc[1] = fmaf(w, f0.y, acc[1]);
                acc[2] = fmaf(w, f1.x, acc[2]);
                acc[3] = fmaf(w, f1.y, acc[3]);
                acc[4] = fmaf(w, f2.x, acc[4]);
                acc[5] = fmaf(w, f2.y, acc[5]);
                acc[6] = fmaf(w, f3.x, acc[6]);
                acc[7] = fmaf(w, f3.y, acc[7]);
            }
        }
    }

#pragma unroll
    for (int c = 0; c < 8; c++) {
        int idx = c * NPTS + p;
        if (idx < out_floats) out[idx] = acc[c];
    }
}

// ---------------- launch -------------------------------------------------------
extern "C" void kernel_launch(void* const* d_in, const int* in_sizes, int n_in,
                              void* d_out, int out_size) {
    const float* img_r = (const float*)d_in[0];
    const float* img_i = (const float*)d_in[1];
    const float* trj   = (const float*)d_in[2];
    float* out = (float*)d_out;

    double beta_d = PI_F * sqrt(12.16);
    float beta  = (float)beta_d;
    float beta2 = (float)(beta_d * beta_d);

    int setup_n = KFP*OS + M2*KFP + C_CH*MR*KFP;
    setup_kernel<<<(setup_n + 255) / 256, 256>>>(img_r, img_i, beta2);

    dim3 g1(3, MR/32, C_CH);       // (3, 10, 8) = 240 blocks
    stage1_kernel<<<g1, 128>>>();
    dim3 g2(OS/64, 6, C_CH);       // (5, 6, 8) = 240 blocks, m=0..191
    stage2_kernel<<<g2, 128>>>();

    interp_kernel<<<(NPTS + 255) / 256, 256>>>(trj, out, beta, out_size);
}

// round 17
// speedup vs baseline: 2.0759x; 1.2648x over previous
#include <cuda_runtime.h>
#include <math.h>

#define C_CH 8
#define NH 256
#define NW 256
#define OS 320
#define OSP 326          // padded y-dim: rows 320..325 replicate 0..5 (no dy wrap)
#define KF 129
#define KFP 144
#define MS 160           // rows per set in stage1 (129 padded to 5x32)
#define MR (2*MS)        // 320 stage1 rows total (U-set then V-set)
#define M2 192
#define NPTS (64*4096)
#define PI_F 3.14159265358979323846
#define INV6 (1.0f / 6.0f)

// ---------------- scratch (static device arrays; no allocation) ----------------
__device__ float2 d_W1[KFP*OS];               // stage1 B: rows 32..160 of W, zero-pad
__device__ float2 d_W2[M2*KFP];               // stage2 A: W[m][32+hf], zero-pad hf>128
__device__ float  d_SX[C_CH*MR*KFP];          // stage1 A plane 1 (real)
__device__ float  d_EX[C_CH*MR*KFP];          // stage1 A plane 2 (real)
__device__ float  d_U[C_CH*KFP*OS];           // U = Re-folded transform rows
__device__ float  d_V[C_CH*KFP*OS];           // V = Im-folded transform rows
__device__ __align__(16) float d_Pg[OS*OSP*C_CH]; // re(spectrum) fp32, [x][y_pad][c]

// ---------------- setup: W1 + W2 + prep fold, one launch ----------------------
__global__ void setup_kernel(const float* __restrict__ img_r,
                             const float* __restrict__ img_i,
                             float beta2) {
    int idx = blockIdx.x * blockDim.x + threadIdx.x;
    if (idx < KFP*OS) {
        int jf = idx / OS, k = idx % OS;
        if (jf > 128) { d_W1[idx] = make_float2(0.f, 0.f); return; }
        int row = 32 + jf;
        int r = (row * k) % OS;
        float s, c;
        sincospif(2.0f * (float)r / (float)OS, &s, &c);
        float sign = ((row + k) & 1) ? -1.0f : 1.0f;
        d_W1[idx] = make_float2(sign * c, -sign * s);
        return;
    }
    idx -= KFP*OS;
    if (idx < M2*KFP) {
        int m = idx / KFP, hf = idx % KFP;
        if (hf > 128) { d_W2[idx] = make_float2(0.f, 0.f); return; }
        int col = 32 + hf;
        int r = (m * col) % OS;
        float s, c;
        sincospif(2.0f * (float)r / (float)OS, &s, &c);
        float sign = ((m + col) & 1) ? -1.0f : 1.0f;
        d_W2[idx] = make_float2(sign * c, -sign * s);
        return;
    }
    idx -= M2*KFP;
    if (idx >= C_CH*MR*KFP) return;
    // ---- prep: apodize + scale + fold in BOTH h and j ----
    int jf = idx % KFP;
    int r  = (idx / KFP) % MR;
    int c  = idx / (KFP * MR);
    int set = r / MS;
    int hf  = r % MS;
    if (jf > 128 || hf > 128) { d_SX[idx] = 0.f; d_EX[idx] = 0.f; return; }
    float u, arg;
    u   = (float)PI_F * 6.0f * (float)(hf - 128) / 320.0f;
    arg = sqrtf(beta2 - u*u);
    float fh = arg / sinhf(arg);
    u   = (float)PI_F * 6.0f * (float)(jf - 128) / 320.0f;
    arg = sqrtf(beta2 - u*u);
    float fj = arg / sinhf(arg);
    float s = fh * fj * (1.0f / 256.0f);

    bool hasJm = (jf >= 1 && jf <= 127);
    bool hasHp = (hf >= 1 && hf <= 127);
    int b1 = (c * NH + hf) * NW;
    int b2 = (c * NH + (256 - hf)) * NW;
    int jm = 256 - jf;

    float ar1 = img_r[b1 + jf],              ai1 = img_i[b1 + jf];
    float am1 = hasJm ? img_r[b1 + jm] : 0.f, bm1 = hasJm ? img_i[b1 + jm] : 0.f;
    float ar2 = hasHp ? img_r[b2 + jf] : 0.f, ai2 = hasHp ? img_i[b2 + jf] : 0.f;
    float am2 = (hasHp && hasJm) ? img_r[b2 + jm] : 0.f;
    float bm2 = (hasHp && hasJm) ? img_i[b2 + jm] : 0.f;

    float sx, ex;
    if (set == 0) {
        sx =  s * (ar1 + am1 + ar2 + am2);
        ex = -s * (ai1 - bm1 + ai2 - bm2);
    } else {
        sx =  s * (ai1 + bm1 - ai2 - bm2);
        ex =  s * (ar1 - am1 - ar2 + am2);
    }
    d_SX[idx] = sx;
    d_EX[idx] = ex;
}

// ========== stage1: real GEMM with col-pair fold (M=320, N=192p, K=144) ========
__global__ void __launch_bounds__(128) stage1_kernel() {
    __shared__ float SXs[2][16][33];
    __shared__ float EXs[2][16][33];
    __shared__ float2 Wv[2][16][64];
    const int c = blockIdx.z;
    const float* __restrict__ Sg = d_SX + (size_t)c * MR * KFP;
    const float* __restrict__ Eg = d_EX + (size_t)c * MR * KFP;

    const int tid = threadIdx.x;
    const int bm = blockIdx.y * 32;
    const int bq = blockIdx.x * 64;
    const int tmi = tid >> 4;
    const int tni = tid & 15;
    const int lak = tid & 15, lam = tid >> 4;
    const int lbn = tid & 63, lbh = tid >> 6;
    const int AMAX = MR*KFP - 1;
    const int BMAX = KFP*OS - 1;

    float P[4][4], Q[4][4];
#pragma unroll
    for (int i = 0; i < 4; i++)
#pragma unroll
        for (int j = 0; j < 4; j++) { P[i][j] = 0.f; Q[i][j] = 0.f; }

    float rs[4], re_[4];
    float2 rw[8];
#pragma unroll
    for (int p = 0; p < 4; p++) {
        int ia = (bm + lam + p*8) * KFP + lak;
        rs[p]  = Sg[min(ia, AMAX)];
        re_[p] = Eg[min(ia, AMAX)];
    }
#pragma unroll
    for (int p = 0; p < 8; p++)
        rw[p] = d_W1[min((lbh + p*2) * OS + (bq + lbn), BMAX)];
#pragma unroll
    for (int p = 0; p < 4; p++) { SXs[0][lak][lam+p*8] = rs[p]; EXs[0][lak][lam+p*8] = re_[p]; }
#pragma unroll
    for (int p = 0; p < 8; p++) Wv[0][lbh+p*2][lbn] = rw[p];
    __syncthreads();

    const int NT = KFP / 16;   // 9
    for (int t = 0; t < NT; t++) {
        const int cur = t & 1, nxt = cur ^ 1;
        const bool more = (t + 1 < NT);
        if (more) {
            int k0 = (t + 1) * 16;
#pragma unroll
            for (int p = 0; p < 4; p++) {
                int ia = (bm + lam + p*8) * KFP + (k0 + lak);
                rs[p]  = Sg[min(ia, AMAX)];
                re_[p] = Eg[min(ia, AMAX)];
            }
#pragma unroll
            for (int p = 0; p < 8; p++)
                rw[p] = d_W1[min((k0 + lbh + p*2) * OS + (bq + lbn), BMAX)];
        }
#pragma unroll
        for (int kk = 0; kk < 16; kk++) {
            float sx[4], ex[4];
            float2 w[4];
#pragma unroll
            for (int i = 0; i < 4; i++) { sx[i] = SXs[cur][kk][tmi+8*i]; ex[i] = EXs[cur][kk][tmi+8*i]; }
#pragma unroll
            for (int j = 0; j < 4; j++) w[j] = Wv[cur][kk][tni+16*j];
#pragma unroll
            for (int i = 0; i < 4; i++)
#pragma unroll
                for (int j = 0; j < 4; j++) {
                    P[i][j] = fmaf(sx[i], w[j].x, P[i][j]);
                    Q[i][j] = fmaf(ex[i], w[j].y, Q[i][j]);
                }
        }
        if (more) {
#pragma unroll
            for (int p = 0; p < 4; p++) { SXs[nxt][lak][lam+p*8] = rs[p]; EXs[nxt][lak][lam+p*8] = re_[p]; }
#pragma unroll
            for (int p = 0; p < 8; p++) Wv[nxt][lbh+p*2][lbn] = rw[p];
        }
        __syncthreads();
    }

    const int set = (bm >= MS) ? 1 : 0;
    float* __restrict__ Og = (set ? d_V : d_U) + (size_t)c * KFP * OS;
#pragma unroll
    for (int i = 0; i < 4; i++)
#pragma unroll
        for (int j = 0; j < 4; j++) {
            int row = bm + tmi + 8*i;
            int hf  = row - set * MS;
            if (hf >= KFP) continue;
            int q = bq + tni + 16*j;
            Og[hf * OS + q] = P[i][j] + Q[i][j];
            if (q >= 1 && q <= 128)
                Og[hf * OS + (320 - q)] = P[i][j] - Q[i][j];
        }
}

// ========== stage2: doubly-folded real GEMM -> padded [x][y_pad][c] grid =======
__global__ void __launch_bounds__(128) stage2_kernel() {
    __shared__ float Wr2s[2][16][33];
    __shared__ float Wi2s[2][16][33];
    __shared__ float Trs[2][16][64];
    __shared__ float Tis[2][16][64];
    const int c = blockIdx.z;
    const float2* __restrict__ A = d_W2;
    const float*  __restrict__ BU = d_U + (size_t)c * KFP * OS;
    const float*  __restrict__ BV = d_V + (size_t)c * KFP * OS;

    const int tid = threadIdx.x;
    const int bm = blockIdx.y * 32;   // m in [0,192)
    const int bn = blockIdx.x * 64;
    const int tmi = tid >> 4;
    const int tni = tid & 15;
    const int lak = tid & 15, lam = tid >> 4;
    const int lbn = tid & 63, lbh = tid >> 6;
    const int AMAX = M2*KFP - 1;
    const int BMAX = KFP*OS - 1;

    float accP[4][4], accQ[4][4];
#pragma unroll
    for (int i = 0; i < 4; i++)
#pragma unroll
        for (int j = 0; j < 4; j++) { accP[i][j] = 0.f; accQ[i][j] = 0.f; }

    float2 ra[4];
    float rbu[8], rbv[8];
#pragma unroll
    for (int p = 0; p < 4; p++)
        ra[p] = A[min((bm + lam + p*8) * KFP + lak, AMAX)];
#pragma unroll
    for (int p = 0; p < 8; p++) {
        int ib = min((lbh + p*2) * OS + (bn + lbn), BMAX);
        rbu[p] = BU[ib];
        rbv[p] = BV[ib];
    }
#pragma unroll
    for (int p = 0; p < 4; p++) { Wr2s[0][lak][lam+p*8] = ra[p].x; Wi2s[0][lak][lam+p*8] = ra[p].y; }
#pragma unroll
    for (int p = 0; p < 8; p++) { Trs[0][lbh+p*2][lbn] = rbu[p]; Tis[0][lbh+p*2][lbn] = rbv[p]; }
    __syncthreads();

    const int NT = KFP / 16;   // 9
    for (int t = 0; t < NT; t++) {
        const int cur = t & 1, nxt = cur ^ 1;
        const bool more = (t + 1 < NT);
        if (more) {
            int k0 = (t + 1) * 16;
#pragma unroll
            for (int p = 0; p < 4; p++)
                ra[p] = A[min((bm + lam + p*8) * KFP + (k0 + lak), AMAX)];
#pragma unroll
            for (int p = 0; p < 8; p++) {
                int ib = min((k0 + lbh + p*2) * OS + (bn + lbn), BMAX);
                rbu[p] = BU[ib];
                rbv[p] = BV[ib];
            }
        }
#pragma unroll
        for (int kk = 0; kk < 16; kk++) {
            float wr[4], wi[4], tr[4], ti[4];
#pragma unroll
            for (int i = 0; i < 4; i++) { wr[i] = Wr2s[cur][kk][tmi+8*i]; wi[i] = Wi2s[cur][kk][tmi+8*i]; }
#pragma unroll
            for (int j = 0; j < 4; j++) { tr[j] = Trs[cur][kk][tni+16*j]; ti[j] = Tis[cur][kk][tni+16*j]; }
#pragma unroll
            for (int i = 0; i < 4; i++)
#pragma unroll
                for (int j = 0; j < 4; j++) {
                    accP[i][j] = fmaf(wr[i], tr[j], accP[i][j]);
                    accQ[i][j] = fmaf(wi[i], ti[j], accQ[i][j]);
                }
        }
        if (more) {
#pragma unroll
            for (int p = 0; p < 4; p++) { Wr2s[nxt][lak][lam+p*8] = ra[p].x; Wi2s[nxt][lak][lam+p*8] = ra[p].y; }
#pragma unroll
            for (int p = 0; p < 8; p++) { Trs[nxt][lbh+p*2][lbn] = rbu[p]; Tis[nxt][lbh+p*2][lbn] = rbv[p]; }
        }
        __syncthreads();
    }
#pragma unroll
    for (int i = 0; i < 4; i++)
#pragma unroll
        for (int j = 0; j < 4; j++) {
            int m   = bm + tmi + 8*i;
            int col = bn + tni + 16*j;
            float gv = accP[i][j] - accQ[i][j];
            d_Pg[(m * OSP + col) * C_CH + c] = gv;
            if (col < 6) d_Pg[(m * OSP + 320 + col) * C_CH + c] = gv;  // replica
            int mm = 320 - m;
            if (mm >= 192 && mm < 320) {
                float gv2 = accP[i][j] + accQ[i][j];
                d_Pg[(mm * OSP + col) * C_CH + c] = gv2;
                if (col < 6) d_Pg[(mm * OSP + 320 + col) * C_CH + c] = gv2;
            }
        }
}

// ---------------- Kaiser-Bessel i0 (Abramowitz & Stegun 9.8.1 / 9.8.2) --------
__device__ __forceinline__ float i0f(float x) {
    if (x < 3.75f) {
        float t = x * (1.0f / 3.75f);
        t *= t;
        return 1.0f + t*(3.5156229f + t*(3.0899424f + t*(1.2067492f +
                     t*(0.2659732f + t*(0.0360768f + t*0.0045813f)))));
    } else {
        float t = 3.75f / x;
        float p = 0.39894228f + t*(0.01328592f + t*(0.00225319f +
                  t*(-0.00157565f + t*(0.00916281f + t*(-0.02057706f +
                  t*(0.02635537f + t*(-0.01647633f + t*0.00392377f)))))));
        return expf(x) * rsqrtf(x) * p;
    }
}

// ---------------- KB interpolation: cooperative 8-lanes-per-point gather -------
// Warp = 4 points x 8 lanes. Per dx column: 6 dy taps are 192B contiguous in
// d_Pg; lanes fetch 16B chunks (rounds of 8 + 4 chunks) -> lines shared.
__global__ void __launch_bounds__(256) interp_kernel(const float* __restrict__ trj,
                              float* __restrict__ out, float beta,
                              int out_floats) {
    const unsigned FULL = 0xffffffffu;
    int t   = blockIdx.x * blockDim.x + threadIdx.x;
    int p   = t >> 3;           // point index
    int sub = t & 7;            // lane within point-group
    if (p >= NPTS) return;

    float tx = trj[2*p], ty = trj[2*p + 1];
    float cx = __fadd_rn(__fmul_rn(tx, 1.25f), 160.0f);
    float cy = __fadd_rn(__fmul_rn(ty, 1.25f), 160.0f);
    float x0 = ceilf(cx - 3.0f);
    float y0 = ceilf(cy - 3.0f);

    // distributed weight evals:
    // evalA: sub 0-5 -> wx[sub];  sub 6-7 -> wy[4], wy[5]
    // evalB: sub 0-3 -> wy[sub]   (sub 4-7 compute unused values)
    float posA = (sub < 6) ? (x0 + (float)sub) : (y0 + (float)(sub - 2)); // 6->y0+4, 7->y0+5
    float refA = (sub < 6) ? cx : cy;
    float uA   = (posA - refA) * (1.0f / 3.0f);
    float evalA = i0f(beta * sqrtf(fmaxf(1.0f - uA*uA, 0.0f))) * INV6;

    float posB = y0 + (float)(sub & 3);
    float uB   = (posB - cy) * (1.0f / 3.0f);
    float evalB = i0f(beta * sqrtf(fmaxf(1.0f - uB*uB, 0.0f))) * INV6;

    // ox for this lane's dx (valid sub<6)
    int qx = (int)(x0 + (float)((sub < 6) ? sub : 0)) % OS; if (qx < 0) qx += OS;
    int ox_mine = qx * (OSP * C_CH);
    int y0i = (int)y0 % OS; if (y0i < 0) y0i += OS;
    int ybase = y0i * C_CH;

    int   dy1  = sub >> 1;                 // round-1 tap
    float wy1  = __shfl_sync(FULL, evalB, dy1, 8);
    float wy2  = __shfl_sync(FULL, evalA, 6 + ((sub & 3) >> 1), 8);
    bool  act2 = (sub < 4);

    float a0 = 0.f, a1 = 0.f, a2 = 0.f, a3 = 0.f;

#pragma unroll
    for (int dx = 0; dx < 6; dx++) {
        float wxv = __shfl_sync(FULL, evalA, dx, 8);
        int   oxv = __shfl_sync(FULL, ox_mine, dx, 8);
        const float* colp = d_Pg + (oxv + ybase);

        // round 1: chunks 0..7 = taps dy 0..3 (8 floats/tap, half = sub&1)
        float4 v1 = __ldg(reinterpret_cast<const float4*>(colp + sub * 4));
        float w1 = wxv * wy1;
        a0 = fmaf(w1, v1.x, a0);
        a1 = fmaf(w1, v1.y, a1);
        a2 = fmaf(w1, v1.z, a2);
        a3 = fmaf(w1, v1.w, a3);

        // round 2: chunks 8..11 = taps dy 4,5 (lanes sub<4)
        float4 v2 = make_float4(0.f, 0.f, 0.f, 0.f);
        if (act2) v2 = __ldg(reinterpret_cast<const float4*>(colp + 32 + sub * 4));
        float w2 = wxv * wy2;
        a0 = fmaf(w2, v2.x, a0);
        a1 = fmaf(w2, v2.y, a1);
        a2 = fmaf(w2, v2.z, a2);
        a3 = fmaf(w2, v2.w, a3);
    }

    // reduce across lanes of same channel-half (sub&1) within the 8-lane group
    a0 += __shfl_xor_sync(FULL, a0, 2, 8);
    a1 += __shfl_xor_sync(FULL, a1, 2, 8);
    a2 += __shfl_xor_sync(FULL, a2, 2, 8);
    a3 += __shfl_xor_sync(FULL, a3, 2, 8);
    a0 += __shfl_xor_sync(FULL, a0, 4, 8);
    a1 += __shfl_xor_sync(FULL, a1, 4, 8);
    a2 += __shfl_xor_sync(FULL, a2, 4, 8);
    a3 += __shfl_xor_sync(FULL, a3, 4, 8);

    if (sub < 2) {
        int cbase = sub * 4;
        int i0_ = (cbase + 0) * NPTS + p;
        int i1_ = (cbase + 1) * NPTS + p;
        int i2_ = (cbase + 2) * NPTS + p;
        int i3_ = (cbase + 3) * NPTS + p;
        if (i0_ < out_floats) out[i0_] = a0;
        if (i1_ < out_floats) out[i1_] = a1;
        if (i2_ < out_floats) out[i2_] = a2;
        if (i3_ < out_floats) out[i3_] = a3;
    }
}

// ---------------- launch -------------------------------------------------------
extern "C" void kernel_launch(void* const* d_in, const int* in_sizes, int n_in,
                              void* d_out, int out_size) {
    const float* img_r = (const float*)d_in[0];
    const float* img_i = (const float*)d_in[1];
    const float* trj   = (const float*)d_in[2];
    float* out = (float*)d_out;

    double beta_d = PI_F * sqrt(12.16);
    float beta  = (float)beta_d;
    float beta2 = (float)(beta_d * beta_d);

    int setup_n = KFP*OS + M2*KFP + C_CH*MR*KFP;
    setup_kernel<<<(setup_n + 255) / 256, 256>>>(img_r, img_i, beta2);

    dim3 g1(3, MR/32, C_CH);       // (3, 10, 8) = 240 blocks
    stage1_kernel<<<g1, 128>>>();
    dim3 g2(OS/64, 6, C_CH);       // (5, 6, 8) = 240 blocks, m=0..191
    stage2_kernel<<<g2, 128>>>();

    int ithreads = NPTS * 8;       // 8 lanes per point
    interp_kernel<<<(ithreads + 255) / 256, 256>>>(trj, out, beta, out_size);
}